// round 1
// baseline (speedup 1.0000x reference)
#include <cuda_runtime.h>

// Sizes (fixed by the problem)
#define D 64
#define S 64
#define L 64
#define W 300
#define H 300
#define NROWS (D*S)          // 4096
#define NEGV (-9999999.0f)

// ---------------- device scratch (no allocation allowed) ----------------
__device__ float g_enc[NROWS * H];
__device__ float g_P  [NROWS * H];
__device__ float g_C  [NROWS * H];
__device__ float g_tmp[NROWS * H];
__device__ float g_X  [NROWS * 3 * H];
__device__ float g_ri [NROWS * H];
__device__ float g_rs [NROWS];
__device__ float g_fin[D * H];

// =====================================================================
// Generic SGEMM: Cout[M,N] = act( A[M,K] @ B[N,K]^T + bias[N] )
// A rows optionally gathered: row m -> A[ idx[m*idxStride] * K + k ]
// Block tile 64x64, BK=16, 256 threads, 4x4 per-thread microtile.
// =====================================================================
#define BM 64
#define BN 64
#define BK 16

__global__ void sgemm_kernel(const float* __restrict__ A,
                             const int*   __restrict__ idx, int idxStride,
                             const float* __restrict__ B,   // [N,K] row-major
                             const float* __restrict__ bias,
                             float* __restrict__ Cout,
                             int M, int N, int K, int do_lrelu)
{
    __shared__ float As[BK][BM + 1];
    __shared__ float Bs[BK][BN + 1];

    const int tid = threadIdx.x;
    const int tx = tid & 15;
    const int ty = tid >> 4;
    const int m0 = blockIdx.y * BM;
    const int n0 = blockIdx.x * BN;

    const int arow = tid >> 2;          // 0..63
    const int acol = (tid & 3) * 4;     // 0,4,8,12

    long aoff;
    if (idx) aoff = (long)idx[(long)(m0 + arow) * idxStride] * K;
    else     aoff = (long)(m0 + arow) * K;

    const int  nrow = n0 + arow;
    const long boff = (long)nrow * K;

    float acc[4][4] = {};

    for (int k0 = 0; k0 < K; k0 += BK) {
        #pragma unroll
        for (int u = 0; u < 4; u++) {
            int k = k0 + acol + u;
            As[acol + u][arow] = (k < K) ? A[aoff + k] : 0.f;
            Bs[acol + u][arow] = (nrow < N && k < K) ? B[boff + k] : 0.f;
        }
        __syncthreads();

        #pragma unroll
        for (int kk = 0; kk < BK; kk++) {
            float a[4], b[4];
            #pragma unroll
            for (int i = 0; i < 4; i++) a[i] = As[kk][ty * 4 + i];
            #pragma unroll
            for (int j = 0; j < 4; j++) b[j] = Bs[kk][tx * 4 + j];
            #pragma unroll
            for (int i = 0; i < 4; i++)
                #pragma unroll
                for (int j = 0; j < 4; j++)
                    acc[i][j] += a[i] * b[j];
        }
        __syncthreads();
    }

    #pragma unroll
    for (int i = 0; i < 4; i++) {
        int m = m0 + ty * 4 + i;
        if (m >= M) continue;
        #pragma unroll
        for (int j = 0; j < 4; j++) {
            int n = n0 + tx * 4 + j;
            if (n >= N) continue;
            float v = acc[i][j] + bias[n];
            if (do_lrelu) v = (v > 0.f) ? v : 0.01f * v;
            Cout[(long)m * N + n] = v;
        }
    }
}

// =====================================================================
// Attention raw scores: A[d,i,j] = sum_h P[d,i,h] * C[d,j,h]
// One block per d. 256 threads, 4x4 microtile over the 64x64 output.
// =====================================================================
__global__ void attn_scores_kernel(const float* __restrict__ P,
                                   const float* __restrict__ Cm,
                                   float* __restrict__ Araw)
{
    const int d = blockIdx.x;
    __shared__ float Ps[32][65];
    __shared__ float Cs[32][65];

    const int tid = threadIdx.x;
    const int tx = tid & 15;
    const int ty = tid >> 4;
    const float* Pd = P  + (long)d * S * H;
    const float* Cd = Cm + (long)d * S * H;

    float acc[4][4] = {};

    for (int k0 = 0; k0 < H; k0 += 32) {
        for (int u = tid; u < 64 * 32; u += 256) {
            int r = u >> 5;
            int k = u & 31;
            bool ok = (k0 + k) < H;
            Ps[k][r] = ok ? Pd[r * H + k0 + k] : 0.f;
            Cs[k][r] = ok ? Cd[r * H + k0 + k] : 0.f;
        }
        __syncthreads();
        #pragma unroll
        for (int kk = 0; kk < 32; kk++) {
            float a[4], b[4];
            #pragma unroll
            for (int i = 0; i < 4; i++) a[i] = Ps[kk][ty * 4 + i];
            #pragma unroll
            for (int j = 0; j < 4; j++) b[j] = Cs[kk][tx * 4 + j];
            #pragma unroll
            for (int i = 0; i < 4; i++)
                #pragma unroll
                for (int j = 0; j < 4; j++)
                    acc[i][j] += a[i] * b[j];
        }
        __syncthreads();
    }

    #pragma unroll
    for (int i = 0; i < 4; i++)
        #pragma unroll
        for (int j = 0; j < 4; j++)
            Araw[(long)d * S * S + (ty * 4 + i) * S + (tx * 4 + j)] = acc[i][j];
}

// =====================================================================
// Mask diagonal + softmax over axis=1 (over i, per (d,j)), in place.
// grid (S, D), 32 threads; each lane owns i=lane and i=lane+32.
// =====================================================================
__global__ void softmax_col_kernel(float* __restrict__ Adata)
{
    const int j = blockIdx.x;
    const int d = blockIdx.y;
    const int lane = threadIdx.x;
    float* base = Adata + (long)d * S * S + j;

    float v0 = base[lane * S];
    float v1 = base[(lane + 32) * S];
    if (lane == j)      v0 = NEGV;
    if (lane + 32 == j) v1 = NEGV;

    float m = fmaxf(v0, v1);
    #pragma unroll
    for (int o = 16; o; o >>= 1) m = fmaxf(m, __shfl_xor_sync(0xffffffffu, m, o));
    float e0 = expf(v0 - m), e1 = expf(v1 - m);
    float s = e0 + e1;
    #pragma unroll
    for (int o = 16; o; o >>= 1) s += __shfl_xor_sync(0xffffffffu, s, o);
    float inv = 1.f / s;
    base[lane * S]        = e0 * inv;
    base[(lane + 32) * S] = e1 * inv;
}

// rs[d,i] = sum_j A[d,i,j]
__global__ void rowsum_kernel(const float* __restrict__ Adata, float* __restrict__ rs)
{
    const int d = blockIdx.x;
    const int i = threadIdx.x;
    const float* row = Adata + (long)d * S * S + i * S;
    float s = 0.f;
    #pragma unroll 8
    for (int j = 0; j < S; j++) s += row[j];
    rs[d * S + i] = s;
}

// scores = enc @ w_root + b_root ; fri = softmax over s (per d)
__global__ void fri_kernel(const float* __restrict__ enc,
                           const float* __restrict__ w_root,
                           const float* __restrict__ b_root,
                           float* __restrict__ fri)
{
    const int d = blockIdx.x;
    const int s = threadIdx.x;   // 64
    const float* e = enc + (long)(d * S + s) * H;
    float acc = b_root[0];
    for (int h = 0; h < H; h++) acc += e[h] * w_root[h];

    __shared__ float sc[S];
    sc[s] = acc;
    __syncthreads();
    float m = -1e30f;
    for (int t = 0; t < S; t++) m = fmaxf(m, sc[t]);
    float ex = expf(acc - m);
    __shared__ float es[S];
    es[s] = ex;
    __syncthreads();
    float sum = 0.f;
    for (int t = 0; t < S; t++) sum += es[t];
    fri[d * S + s] = ex / sum;
}

// tmp[d,i,h] = sum_k A[d,k,i] * enc[d,k,h]   (one block per d)
__global__ void tmp_gemm_kernel(const float* __restrict__ Adata,
                                const float* __restrict__ enc,
                                float* __restrict__ tmp)
{
    const int d = blockIdx.x;
    __shared__ float As[64][65];   // As[k][i]
    __shared__ float Es[64][65];   // Es[k][h]
    const int tid = threadIdx.x;
    const int tx = tid & 15;
    const int ty = tid >> 4;
    const float* Ad = Adata + (long)d * S * S;
    const float* Ed = enc   + (long)d * S * H;

    for (int u = tid; u < S * S; u += 256) As[u >> 6][u & 63] = Ad[u];

    for (int h0 = 0; h0 < H; h0 += 64) {
        __syncthreads();
        for (int u = tid; u < 64 * 64; u += 256) {
            int k = u >> 6, h = u & 63;
            Es[k][h] = (h0 + h < H) ? Ed[k * H + h0 + h] : 0.f;
        }
        __syncthreads();
        float acc[4][4] = {};
        #pragma unroll 8
        for (int k = 0; k < 64; k++) {
            float a[4], b[4];
            #pragma unroll
            for (int i = 0; i < 4; i++) a[i] = As[k][ty * 4 + i];
            #pragma unroll
            for (int j = 0; j < 4; j++) b[j] = Es[k][tx * 4 + j];
            #pragma unroll
            for (int i = 0; i < 4; i++)
                #pragma unroll
                for (int j = 0; j < 4; j++)
                    acc[i][j] += a[i] * b[j];
        }
        #pragma unroll
        for (int i = 0; i < 4; i++)
            #pragma unroll
            for (int j = 0; j < 4; j++) {
                int h = h0 + tx * 4 + j;
                if (h < H)
                    tmp[(long)(d * S + ty * 4 + i) * H + h] = acc[i][j];
            }
    }
}

// X = concat(enc, tmp + fri*root_embed, enc*rs) along feature dim
__global__ void build_x_kernel(const float* __restrict__ enc,
                               const float* __restrict__ tmp,
                               const float* __restrict__ fri,
                               const float* __restrict__ rs,
                               const float* __restrict__ root_embed,
                               float* __restrict__ X)
{
    int id = blockIdx.x * blockDim.x + threadIdx.x;
    if (id >= NROWS * H) return;
    int m = id / H, h = id - m * H;
    float e = enc[id];
    X[(long)m * (3 * H) + h]         = e;
    X[(long)m * (3 * H) + H + h]     = tmp[id] + fri[m] * root_embed[h];
    X[(long)m * (3 * H) + 2 * H + h] = e * rs[m];
}

// final[d,h] = mean over s of ri[d*S+s, h]
__global__ void mean_kernel(const float* __restrict__ ri, float* __restrict__ fin)
{
    const int d = blockIdx.x;
    const int h = threadIdx.x;
    if (h >= H) return;
    float sum = 0.f;
    for (int s = 0; s < S; s++) sum += ri[(long)(d * S + s) * H + h];
    fin[d * H + h] = sum * (1.f / 64.f);
}

// out[d,c] = final[d] . W_cls[c] + b_cls[c]   (1 block, 128 threads)
__global__ void cls_kernel(const float* __restrict__ fin,
                           const float* __restrict__ Wc,
                           const float* __restrict__ bc,
                           float* __restrict__ out)
{
    int t = threadIdx.x;
    int d = t >> 1, c = t & 1;
    const float* f = fin + d * H;
    const float* w = Wc + c * H;
    float acc = bc[c];
    for (int h = 0; h < H; h++) acc += f[h] * w[h];
    out[d * 2 + c] = acc;
}

// =====================================================================
extern "C" void kernel_launch(void* const* d_in, const int* in_sizes, int n_in,
                              void* d_out, int out_size)
{
    const int*   word_indices = (const int*)  d_in[0];
    const float* E            = (const float*)d_in[1];
    const float* W_sent       = (const float*)d_in[2];
    const float* b_sent       = (const float*)d_in[3];
    const float* W_par        = (const float*)d_in[4];
    const float* b_par        = (const float*)d_in[5];
    const float* W_ch         = (const float*)d_in[6];
    const float* b_ch         = (const float*)d_in[7];
    const float* w_root       = (const float*)d_in[8];
    const float* b_root       = (const float*)d_in[9];
    const float* root_embed   = (const float*)d_in[10];
    const float* W_r          = (const float*)d_in[11];
    const float* b_r          = (const float*)d_in[12];
    const float* W_cls        = (const float*)d_in[13];
    const float* b_cls        = (const float*)d_in[14];

    float* out_ptr = (float*)d_out;                 // [D,2]         = 128
    float* A_ptr   = out_ptr + D * 2;               // [D,S,S]       = 262144
    float* fri_ptr = A_ptr + D * S * S;             // [D,S]         = 4096

    float *enc, *Pm, *Cm, *tmp, *X, *ri, *rs, *fin;
    cudaGetSymbolAddress((void**)&enc, g_enc);
    cudaGetSymbolAddress((void**)&Pm,  g_P);
    cudaGetSymbolAddress((void**)&Cm,  g_C);
    cudaGetSymbolAddress((void**)&tmp, g_tmp);
    cudaGetSymbolAddress((void**)&X,   g_X);
    cudaGetSymbolAddress((void**)&ri,  g_ri);
    cudaGetSymbolAddress((void**)&rs,  g_rs);
    cudaGetSymbolAddress((void**)&fin, g_fin);

    dim3 gemm_grid_HW((H + BN - 1) / BN, NROWS / BM);   // (5, 64)

    // 1) enc = lrelu(gather(E, idx) @ W_sent^T + b_sent)  (gather fused: last word, stride L)
    sgemm_kernel<<<gemm_grid_HW, 256>>>(E, word_indices + (L - 1), L,
                                        W_sent, b_sent, enc, NROWS, H, W, 1);
    // 2) P, 3) C
    sgemm_kernel<<<gemm_grid_HW, 256>>>(enc, nullptr, 0, W_par, b_par, Pm, NROWS, H, H, 1);
    sgemm_kernel<<<gemm_grid_HW, 256>>>(enc, nullptr, 0, W_ch,  b_ch,  Cm, NROWS, H, H, 1);

    // 4) raw attention scores -> directly into d_out's A region
    attn_scores_kernel<<<D, 256>>>(Pm, Cm, A_ptr);

    // 5) diag mask + column softmax (axis=1), in place
    softmax_col_kernel<<<dim3(S, D), 32>>>(A_ptr);

    // 6) row sums of A (over j)
    rowsum_kernel<<<D, S>>>(A_ptr, rs);

    // 7) fri = softmax(enc @ w_root + b_root) -> directly into d_out
    fri_kernel<<<D, S>>>(enc, w_root, b_root, fri_ptr);

    // 8) tmp[d,i,h] = sum_k A[d,k,i] enc[d,k,h]
    tmp_gemm_kernel<<<D, 256>>>(A_ptr, enc, tmp);

    // 9) X = concat(enc, tmp + fri*root_embed, enc*rs)
    build_x_kernel<<<(NROWS * H + 255) / 256, 256>>>(enc, tmp, fri_ptr, rs, root_embed, X);

    // 10) ri = lrelu(X @ W_r^T + b_r)   (K = 900)
    sgemm_kernel<<<gemm_grid_HW, 256>>>(X, nullptr, 0, W_r, b_r, ri, NROWS, H, 3 * H, 1);

    // 11) final = mean over s
    mean_kernel<<<D, 320>>>(ri, fin);

    // 12) out = final @ W_cls^T + b_cls
    cls_kernel<<<1, 128>>>(fin, W_cls, b_cls, out_ptr);
}

// round 2
// speedup vs baseline: 2.0721x; 2.0721x over previous
#include <cuda_runtime.h>

#define D 64
#define S 64
#define L 64
#define W 300
#define H 300
#define NROWS (D*S)          // 4096
#define NEGV (-9999999.0f)

// ---------------- device scratch (no allocation allowed) ----------------
__device__ float g_enc[NROWS * H];
__device__ float g_P  [NROWS * H];
__device__ float g_C  [NROWS * H];
__device__ float g_tmp[NROWS * H];
__device__ float g_X  [NROWS * 3 * H];
__device__ float g_rs [NROWS];
__device__ float g_fin[D * H];

__device__ __forceinline__ float lrelu_f(float x) { return x > 0.f ? x : 0.01f * x; }

__device__ __forceinline__ unsigned f2tf32(float f) {
    unsigned u;
    asm("cvt.rna.tf32.f32 %0, %1;" : "=r"(u) : "f"(f));
    return u;
}

__device__ __forceinline__ void mma8(float* c, const unsigned* a, const unsigned* b) {
    asm volatile(
        "mma.sync.aligned.m16n8k8.row.col.f32.tf32.tf32.f32 "
        "{%0,%1,%2,%3}, {%4,%5,%6,%7}, {%8,%9}, {%0,%1,%2,%3};"
        : "+f"(c[0]), "+f"(c[1]), "+f"(c[2]), "+f"(c[3])
        : "r"(a[0]), "r"(a[1]), "r"(a[2]), "r"(a[3]), "r"(b[0]), "r"(b[1]));
}

// =====================================================================
// TF32 tensor-core GEMM: Out[M,N] = lrelu( A[M,K] @ B[N,K]^T + bias[N] )
// Block tile 128x64, BK=16, 256 threads (8 warps, 4x2 warp grid,
// warp tile 32x32 = 2x4 mma m16n8k8).
// GATHER: A row m -> A[ idx[m*idxStride]*K + k ]
// MEAN:   instead of storing rows, reduce columns over each 64-row group
//         (a document) and write fin[d][col] = colmean (after lrelu).
// blockIdx.z==1 selects the (B1,bias1,Out1) triple (for fused P/C).
// =====================================================================
#define BM 128
#define BN 64
#define BK 16
#define BKP 20   // padded k-stride: conflict-free frag loads + 16B alignment

template<bool GATHER, bool MEAN>
__global__ void gemm_tf32_kernel(
    const float* __restrict__ Abase, const int* __restrict__ idx, int idxStride,
    const float* __restrict__ B0, const float* __restrict__ bias0, float* __restrict__ Out0,
    const float* __restrict__ B1, const float* __restrict__ bias1, float* __restrict__ Out1,
    int N, int K)
{
    const float* Bw   = B0;
    const float* bias = bias0;
    float*       Out  = Out0;
    if (B1 != nullptr && blockIdx.z == 1) { Bw = B1; bias = bias1; Out = Out1; }

    __shared__ __align__(16) unsigned As[BM][BKP];
    __shared__ __align__(16) unsigned Bs[BN][BKP];
    __shared__ float red[2][BN];

    const int tid  = threadIdx.x;
    const int lane = tid & 31;
    const int wid  = tid >> 5;     // 0..7
    const int wm   = wid >> 1;     // 0..3  (M direction)
    const int wn   = wid & 1;      // 0..1  (N direction)
    const int m0   = blockIdx.y * BM;
    const int n0   = blockIdx.x * BN;

    if (MEAN && tid < 2 * BN) ((float*)red)[tid] = 0.f;

    // loader indices
    const int am0 = tid >> 2;           // 0..63 (also +64)
    const int ac  = (tid & 3) * 4;      // 0,4,8,12
    long aoff0, aoff1;
    if (GATHER) {
        aoff0 = (long)idx[(long)(m0 + am0) * idxStride] * K;
        aoff1 = (long)idx[(long)(m0 + am0 + 64) * idxStride] * K;
    } else {
        aoff0 = (long)(m0 + am0) * K;
        aoff1 = (long)(m0 + am0 + 64) * K;
    }
    const int  bn     = tid >> 2;       // 0..63
    const bool bvalid = (n0 + bn) < N;
    const long boff   = (long)(n0 + bn) * K;

    float acc[2][4][4];
    #pragma unroll
    for (int i = 0; i < 2; i++)
        #pragma unroll
        for (int j = 0; j < 4; j++)
            #pragma unroll
            for (int q = 0; q < 4; q++) acc[i][j][q] = 0.f;

    const int lr = lane >> 2;
    const int lc = lane & 3;

    for (int k0 = 0; k0 < K; k0 += BK) {
        if (k0 + BK <= K) {
            float4 a0 = *(const float4*)(Abase + aoff0 + k0 + ac);
            float4 a1 = *(const float4*)(Abase + aoff1 + k0 + ac);
            float4 bv = bvalid ? *(const float4*)(Bw + boff + k0 + ac)
                               : make_float4(0.f, 0.f, 0.f, 0.f);
            uint4 u0 = make_uint4(f2tf32(a0.x), f2tf32(a0.y), f2tf32(a0.z), f2tf32(a0.w));
            uint4 u1 = make_uint4(f2tf32(a1.x), f2tf32(a1.y), f2tf32(a1.z), f2tf32(a1.w));
            uint4 ub = make_uint4(f2tf32(bv.x), f2tf32(bv.y), f2tf32(bv.z), f2tf32(bv.w));
            *(uint4*)&As[am0][ac]      = u0;
            *(uint4*)&As[am0 + 64][ac] = u1;
            *(uint4*)&Bs[bn][ac]       = ub;
        } else {
            #pragma unroll
            for (int u = 0; u < 4; u++) {
                int k = k0 + ac + u;
                As[am0][ac + u]      = (k < K) ? f2tf32(Abase[aoff0 + k]) : 0u;
                As[am0 + 64][ac + u] = (k < K) ? f2tf32(Abase[aoff1 + k]) : 0u;
                Bs[bn][ac + u]       = (bvalid && k < K) ? f2tf32(Bw[boff + k]) : 0u;
            }
        }
        __syncthreads();

        #pragma unroll
        for (int ks = 0; ks < 2; ks++) {
            const int kb = ks * 8;
            unsigned a[2][4], b[4][2];
            #pragma unroll
            for (int mi = 0; mi < 2; mi++) {
                int r = wm * 32 + mi * 16 + lr;
                a[mi][0] = As[r][kb + lc];
                a[mi][1] = As[r + 8][kb + lc];
                a[mi][2] = As[r][kb + lc + 4];
                a[mi][3] = As[r + 8][kb + lc + 4];
            }
            #pragma unroll
            for (int ni = 0; ni < 4; ni++) {
                int c = wn * 32 + ni * 8 + lr;
                b[ni][0] = Bs[c][kb + lc];
                b[ni][1] = Bs[c][kb + lc + 4];
            }
            #pragma unroll
            for (int mi = 0; mi < 2; mi++)
                #pragma unroll
                for (int ni = 0; ni < 4; ni++)
                    mma8(acc[mi][ni], a[mi], b[ni]);
        }
        __syncthreads();
    }

    if (!MEAN) {
        #pragma unroll
        for (int mi = 0; mi < 2; mi++) {
            int r = m0 + wm * 32 + mi * 16 + lr;
            #pragma unroll
            for (int ni = 0; ni < 4; ni++) {
                int cb = n0 + wn * 32 + ni * 8 + 2 * lc;
                float b0v = (cb     < N) ? bias[cb]     : 0.f;
                float b1v = (cb + 1 < N) ? bias[cb + 1] : 0.f;
                if (cb < N) {
                    Out[(long)r * N + cb]       = lrelu_f(acc[mi][ni][0] + b0v);
                    Out[(long)(r + 8) * N + cb] = lrelu_f(acc[mi][ni][2] + b0v);
                }
                if (cb + 1 < N) {
                    Out[(long)r * N + cb + 1]       = lrelu_f(acc[mi][ni][1] + b1v);
                    Out[(long)(r + 8) * N + cb + 1] = lrelu_f(acc[mi][ni][3] + b1v);
                }
            }
        }
    } else {
        __syncthreads();  // red[] zeroed by all before atomics
        const int dl = wm >> 1;   // which document half of the 128-row tile
        #pragma unroll
        for (int ni = 0; ni < 4; ni++) {
            int cb = n0 + wn * 32 + ni * 8 + 2 * lc;
            float b0v = (cb     < N) ? bias[cb]     : 0.f;
            float b1v = (cb + 1 < N) ? bias[cb + 1] : 0.f;
            float s0 = 0.f, s1 = 0.f;
            #pragma unroll
            for (int mi = 0; mi < 2; mi++) {
                s0 += lrelu_f(acc[mi][ni][0] + b0v) + lrelu_f(acc[mi][ni][2] + b0v);
                s1 += lrelu_f(acc[mi][ni][1] + b1v) + lrelu_f(acc[mi][ni][3] + b1v);
            }
            // reduce across the 8 row-groups (lanes differing in lane>>2)
            #pragma unroll
            for (int o = 4; o < 32; o <<= 1) {
                s0 += __shfl_xor_sync(0xffffffffu, s0, o);
                s1 += __shfl_xor_sync(0xffffffffu, s1, o);
            }
            if (lane < 4) {
                atomicAdd(&red[dl][wn * 32 + ni * 8 + 2 * lc],     s0);
                atomicAdd(&red[dl][wn * 32 + ni * 8 + 2 * lc + 1], s1);
            }
        }
        __syncthreads();
        if (tid < 128) {
            int dloc = tid >> 6, c = tid & 63;
            int col = n0 + c;
            if (col < N)
                Out[(long)(blockIdx.y * 2 + dloc) * N + col] = red[dloc][c] * (1.f / 64.f);
        }
    }
}

// =====================================================================
// Fused per-document attention:
//   scores = P @ C^T ; diag mask ; softmax over i ; A -> d_out
//   rs[i] = sum_j A[i][j] ; fri = softmax(enc @ w_root + b_root)
//   tmp[i][h] = sum_k A[k][i] * enc[k][h]
// One block per d, 512 threads.
// =====================================================================
__global__ void attn_fused_kernel(const float* __restrict__ P,
                                  const float* __restrict__ Cm,
                                  const float* __restrict__ enc,
                                  const float* __restrict__ w_root,
                                  const float* __restrict__ b_root,
                                  const float* __restrict__ root_embed,  // unused, kept for symmetry
                                  float* __restrict__ A_out,
                                  float* __restrict__ fri_out,
                                  float* __restrict__ rs_out,
                                  float* __restrict__ tmp_out)
{
    const int d = blockIdx.x;
    const int t = threadIdx.x;          // 0..511
    __shared__ float Ash[64][65];
    __shared__ float Buf[64 * 66];      // scores: P at [64][33], C at +64*33 ; tmp: enc [64][66]
    __shared__ float sred[64];

    const float* Pd = P   + (long)d * S * H;
    const float* Cd = Cm  + (long)d * S * H;
    const float* Ed = enc + (long)d * S * H;

    const int i0 = (t >> 4) * 2;        // 0,2,..,62
    const int j0 = (t & 15) * 4;        // 0,4,..,60

    // ---------- scores: acc[2][4] over (i0+ii, j0+jj) ----------
    float acc[2][4] = {};
    float* Pt = Buf;                    // [64][33]
    float* Ct = Buf + 64 * 33;          // [64][33]
    for (int k0 = 0; k0 < H; k0 += 32) {
        __syncthreads();
        for (int u = t; u < 64 * 32; u += 512) {
            int r = u >> 5, k = u & 31;
            bool ok = (k0 + k) < H;
            Pt[r * 33 + k] = ok ? Pd[r * H + k0 + k] : 0.f;
            Ct[r * 33 + k] = ok ? Cd[r * H + k0 + k] : 0.f;
        }
        __syncthreads();
        #pragma unroll 4
        for (int k = 0; k < 32; k++) {
            float p0 = Pt[i0 * 33 + k];
            float p1 = Pt[(i0 + 1) * 33 + k];
            float c0 = Ct[j0 * 33 + k];
            float c1 = Ct[(j0 + 1) * 33 + k];
            float c2 = Ct[(j0 + 2) * 33 + k];
            float c3 = Ct[(j0 + 3) * 33 + k];
            acc[0][0] += p0 * c0; acc[0][1] += p0 * c1; acc[0][2] += p0 * c2; acc[0][3] += p0 * c3;
            acc[1][0] += p1 * c0; acc[1][1] += p1 * c1; acc[1][2] += p1 * c2; acc[1][3] += p1 * c3;
        }
    }
    __syncthreads();
    #pragma unroll
    for (int ii = 0; ii < 2; ii++)
        #pragma unroll
        for (int jj = 0; jj < 4; jj++) {
            int i = i0 + ii, j = j0 + jj;
            Ash[i][j] = (i == j) ? NEGV : acc[ii][jj];
        }
    __syncthreads();

    // ---------- column softmax (over i) ----------
    if (t < 64) {
        float m = -1e30f;
        for (int i = 0; i < 64; i++) m = fmaxf(m, Ash[i][t]);
        float ssum = 0.f;
        for (int i = 0; i < 64; i++) {
            float e = __expf(Ash[i][t] - m);
            Ash[i][t] = e;
            ssum += e;
        }
        float inv = 1.f / ssum;
        for (int i = 0; i < 64; i++) Ash[i][t] *= inv;
    }
    __syncthreads();

    // ---------- write A, rowsum ----------
    for (int u = t; u < 64 * 64; u += 512)
        A_out[(long)d * 64 * 64 + u] = Ash[u >> 6][u & 63];
    if (t < 64) {
        float s = 0.f;
        #pragma unroll 8
        for (int j = 0; j < 64; j++) s += Ash[t][j];
        rs_out[d * 64 + t] = s;
    }

    // ---------- fri = softmax(enc @ w_root + b_root) ----------
    {
        const int wwid = t >> 5, lane = t & 31;
        const float br0 = b_root[0];
        for (int ss = 0; ss < 4; ss++) {
            int s = wwid * 4 + ss;
            const float* e = Ed + s * H;
            float p = 0.f;
            for (int h = lane; h < H; h += 32) p += e[h] * w_root[h];
            #pragma unroll
            for (int o = 16; o; o >>= 1) p += __shfl_xor_sync(0xffffffffu, p, o);
            if (lane == 0) sred[s] = p + br0;
        }
    }
    __syncthreads();
    float mye = 0.f;
    if (t < 64) {
        float m = -1e30f;
        for (int u = 0; u < 64; u++) m = fmaxf(m, sred[u]);
        mye = __expf(sred[t] - m);
    }
    __syncthreads();
    if (t < 64) sred[t] = mye;
    __syncthreads();
    if (t < 64) {
        float ssum = 0.f;
        for (int u = 0; u < 64; u++) ssum += sred[u];
        fri_out[d * 64 + t] = mye / ssum;
    }

    // ---------- tmp[i][h] = sum_k A[k][i] * enc[k][h] ----------
    float* Et = Buf;                    // [64][66]
    for (int h0 = 0; h0 < H; h0 += 64) {
        __syncthreads();
        for (int u = t; u < 64 * 64; u += 512) {
            int k = u >> 6, h = u & 63;
            Et[k * 66 + h] = (h0 + h < H) ? Ed[k * H + h0 + h] : 0.f;
        }
        __syncthreads();
        float tacc[2][4] = {};
        #pragma unroll 4
        for (int k = 0; k < 64; k++) {
            float a0 = Ash[k][i0];
            float a1 = Ash[k][i0 + 1];
            float e0 = Et[k * 66 + j0];
            float e1 = Et[k * 66 + j0 + 1];
            float e2 = Et[k * 66 + j0 + 2];
            float e3 = Et[k * 66 + j0 + 3];
            tacc[0][0] += a0 * e0; tacc[0][1] += a0 * e1; tacc[0][2] += a0 * e2; tacc[0][3] += a0 * e3;
            tacc[1][0] += a1 * e0; tacc[1][1] += a1 * e1; tacc[1][2] += a1 * e2; tacc[1][3] += a1 * e3;
        }
        #pragma unroll
        for (int ii = 0; ii < 2; ii++)
            #pragma unroll
            for (int hh = 0; hh < 4; hh++) {
                int h = h0 + j0 + hh;
                if (h < H)
                    tmp_out[(long)(d * 64 + i0 + ii) * H + h] = tacc[ii][hh];
            }
    }
}

// X = concat(enc, tmp + fri*root_embed, enc*rs) along feature dim
__global__ void build_x_kernel(const float* __restrict__ enc,
                               const float* __restrict__ tmp,
                               const float* __restrict__ fri,
                               const float* __restrict__ rs,
                               const float* __restrict__ root_embed,
                               float* __restrict__ X)
{
    int id = blockIdx.x * blockDim.x + threadIdx.x;
    if (id >= NROWS * H) return;
    int m = id / H, h = id - m * H;
    float e = enc[id];
    X[(long)m * (3 * H) + h]         = e;
    X[(long)m * (3 * H) + H + h]     = tmp[id] + fri[m] * root_embed[h];
    X[(long)m * (3 * H) + 2 * H + h] = e * rs[m];
}

// out[d,c] = fin[d] . W_cls[c] + b_cls[c]
__global__ void cls_kernel(const float* __restrict__ fin,
                           const float* __restrict__ Wc,
                           const float* __restrict__ bc,
                           float* __restrict__ out)
{
    int t = threadIdx.x;
    int d = t >> 1, c = t & 1;
    const float* f = fin + d * H;
    const float* w = Wc + c * H;
    float a = bc[c];
    for (int h = 0; h < H; h++) a += f[h] * w[h];
    out[d * 2 + c] = a;
}

// =====================================================================
extern "C" void kernel_launch(void* const* d_in, const int* in_sizes, int n_in,
                              void* d_out, int out_size)
{
    const int*   word_indices = (const int*)  d_in[0];
    const float* E            = (const float*)d_in[1];
    const float* W_sent       = (const float*)d_in[2];
    const float* b_sent       = (const float*)d_in[3];
    const float* W_par        = (const float*)d_in[4];
    const float* b_par        = (const float*)d_in[5];
    const float* W_ch         = (const float*)d_in[6];
    const float* b_ch         = (const float*)d_in[7];
    const float* w_root       = (const float*)d_in[8];
    const float* b_root       = (const float*)d_in[9];
    const float* root_embed   = (const float*)d_in[10];
    const float* W_r          = (const float*)d_in[11];
    const float* b_r          = (const float*)d_in[12];
    const float* W_cls        = (const float*)d_in[13];
    const float* b_cls        = (const float*)d_in[14];

    float* out_ptr = (float*)d_out;                 // [D,2]
    float* A_ptr   = out_ptr + D * 2;               // [D,S,S]
    float* fri_ptr = A_ptr + D * S * S;             // [D,S]

    float *enc, *Pm, *Cm, *tmp, *X, *rs, *fin;
    cudaGetSymbolAddress((void**)&enc, g_enc);
    cudaGetSymbolAddress((void**)&Pm,  g_P);
    cudaGetSymbolAddress((void**)&Cm,  g_C);
    cudaGetSymbolAddress((void**)&tmp, g_tmp);
    cudaGetSymbolAddress((void**)&X,   g_X);
    cudaGetSymbolAddress((void**)&rs,  g_rs);
    cudaGetSymbolAddress((void**)&fin, g_fin);

    dim3 gEnc((H + BN - 1) / BN, NROWS / BM, 1);    // (5, 32, 1)
    dim3 gPC ((H + BN - 1) / BN, NROWS / BM, 2);    // (5, 32, 2)

    // 1) enc = lrelu(gather(E, last word) @ W_sent^T + b_sent)
    gemm_tf32_kernel<true, false><<<gEnc, 256>>>(
        E, word_indices + (L - 1), L,
        W_sent, b_sent, enc, nullptr, nullptr, nullptr, H, W);

    // 2) P and C in one batched launch (z picks weights)
    gemm_tf32_kernel<false, false><<<gPC, 256>>>(
        enc, nullptr, 0,
        W_par, b_par, Pm, W_ch, b_ch, Cm, H, H);

    // 3) fused attention: A (-> d_out), rs, fri (-> d_out), tmp
    attn_fused_kernel<<<D, 512>>>(Pm, Cm, enc, w_root, b_root, root_embed,
                                  A_ptr, fri_ptr, rs, tmp);

    // 4) X = concat(enc, tmp + fri*root, enc*rs)
    build_x_kernel<<<(NROWS * H + 255) / 256, 256>>>(enc, tmp, fri_ptr, rs, root_embed, X);

    // 5) ri GEMM with fused lrelu + per-document mean -> fin
    gemm_tf32_kernel<false, true><<<gEnc, 256>>>(
        X, nullptr, 0,
        W_r, b_r, fin, nullptr, nullptr, nullptr, H, 3 * H);

    // 6) out = fin @ W_cls^T + b_cls
    cls_kernel<<<1, 128>>>(fin, W_cls, b_cls, out_ptr);
}

// round 3
// speedup vs baseline: 2.4201x; 1.1680x over previous
#include <cuda_runtime.h>

#define D 64
#define S 64
#define L 64
#define W 300
#define H 300
#define NROWS (D*S)          // 4096
#define NEGV (-9999999.0f)

// ---------------- device scratch (no allocation allowed) ----------------
__device__ float g_enc[NROWS * H];
__device__ float g_P  [NROWS * H];
__device__ float g_C  [NROWS * H];
__device__ float g_Y2 [NROWS * H];
__device__ float g_G  [NROWS * H];
__device__ float g_rs [NROWS];
__device__ float g_fin[D * H];
__device__ float g_v2 [H];

__device__ __forceinline__ float lrelu_f(float x) { return x > 0.f ? x : 0.01f * x; }

__device__ __forceinline__ unsigned f2tf32(float f) {
    unsigned u;
    asm("cvt.rna.tf32.f32 %0, %1;" : "=r"(u) : "f"(f));
    return u;
}

__device__ __forceinline__ void mma8(float* c, const unsigned* a, const unsigned* b) {
    asm volatile(
        "mma.sync.aligned.m16n8k8.row.col.f32.tf32.tf32.f32 "
        "{%0,%1,%2,%3}, {%4,%5,%6,%7}, {%8,%9}, {%0,%1,%2,%3};"
        : "+f"(c[0]), "+f"(c[1]), "+f"(c[2]), "+f"(c[3])
        : "r"(a[0]), "r"(a[1]), "r"(a[2]), "r"(a[3]), "r"(b[0]), "r"(b[1]));
}

#define BM 128
#define BN 64
#define BK 16
#define BKP 20

// =====================================================================
// TF32 GEMM: Out[M,N] = act( A[M,K] @ B[N,K(ld=ldb)]^T + bias[N] )
// z selects among 3 (B,bias,Out) triples; bias==nullptr => linear.
// =====================================================================
template<bool GATHER>
__global__ void gemm_tf32_kernel(
    const float* __restrict__ Abase, const int* __restrict__ idx, int idxStride,
    const float* __restrict__ B0, const float* __restrict__ bias0, float* __restrict__ Out0,
    const float* __restrict__ B1, const float* __restrict__ bias1, float* __restrict__ Out1,
    const float* __restrict__ B2, const float* __restrict__ bias2, float* __restrict__ Out2,
    int N, int K, int ldb0, int ldb1, int ldb2)
{
    const float* Bw   = B0;
    const float* bias = bias0;
    float*       Out  = Out0;
    int          ldb  = ldb0;
    if (blockIdx.z == 1) { Bw = B1; bias = bias1; Out = Out1; ldb = ldb1; }
    if (blockIdx.z == 2) { Bw = B2; bias = bias2; Out = Out2; ldb = ldb2; }
    const bool act = (bias != nullptr);

    __shared__ __align__(16) unsigned As[BM][BKP];
    __shared__ __align__(16) unsigned Bs[BN][BKP];

    const int tid  = threadIdx.x;
    const int lane = tid & 31;
    const int wid  = tid >> 5;
    const int wm   = wid >> 1;
    const int wn   = wid & 1;
    const int m0   = blockIdx.y * BM;
    const int n0   = blockIdx.x * BN;

    const int am0 = tid >> 2;
    const int ac  = (tid & 3) * 4;
    long aoff0, aoff1;
    if (GATHER) {
        aoff0 = (long)idx[(long)(m0 + am0) * idxStride] * K;
        aoff1 = (long)idx[(long)(m0 + am0 + 64) * idxStride] * K;
    } else {
        aoff0 = (long)(m0 + am0) * K;
        aoff1 = (long)(m0 + am0 + 64) * K;
    }
    const int  bn     = tid >> 2;
    const bool bvalid = (n0 + bn) < N;
    const long boff   = (long)(n0 + bn) * ldb;

    float acc[2][4][4];
    #pragma unroll
    for (int i = 0; i < 2; i++)
        #pragma unroll
        for (int j = 0; j < 4; j++)
            #pragma unroll
            for (int q = 0; q < 4; q++) acc[i][j][q] = 0.f;

    const int lr = lane >> 2;
    const int lc = lane & 3;

    for (int k0 = 0; k0 < K; k0 += BK) {
        if (k0 + BK <= K) {
            float4 a0 = *(const float4*)(Abase + aoff0 + k0 + ac);
            float4 a1 = *(const float4*)(Abase + aoff1 + k0 + ac);
            float4 bv = bvalid ? *(const float4*)(Bw + boff + k0 + ac)
                               : make_float4(0.f, 0.f, 0.f, 0.f);
            *(uint4*)&As[am0][ac]      = make_uint4(f2tf32(a0.x), f2tf32(a0.y), f2tf32(a0.z), f2tf32(a0.w));
            *(uint4*)&As[am0 + 64][ac] = make_uint4(f2tf32(a1.x), f2tf32(a1.y), f2tf32(a1.z), f2tf32(a1.w));
            *(uint4*)&Bs[bn][ac]       = make_uint4(f2tf32(bv.x), f2tf32(bv.y), f2tf32(bv.z), f2tf32(bv.w));
        } else {
            #pragma unroll
            for (int u = 0; u < 4; u++) {
                int k = k0 + ac + u;
                As[am0][ac + u]      = (k < K) ? f2tf32(Abase[aoff0 + k]) : 0u;
                As[am0 + 64][ac + u] = (k < K) ? f2tf32(Abase[aoff1 + k]) : 0u;
                Bs[bn][ac + u]       = (bvalid && k < K) ? f2tf32(Bw[boff + k]) : 0u;
            }
        }
        __syncthreads();
        #pragma unroll
        for (int ks = 0; ks < 2; ks++) {
            const int kb = ks * 8;
            unsigned a[2][4], b[4][2];
            #pragma unroll
            for (int mi = 0; mi < 2; mi++) {
                int r = wm * 32 + mi * 16 + lr;
                a[mi][0] = As[r][kb + lc];
                a[mi][1] = As[r + 8][kb + lc];
                a[mi][2] = As[r][kb + lc + 4];
                a[mi][3] = As[r + 8][kb + lc + 4];
            }
            #pragma unroll
            for (int ni = 0; ni < 4; ni++) {
                int c = wn * 32 + ni * 8 + lr;
                b[ni][0] = Bs[c][kb + lc];
                b[ni][1] = Bs[c][kb + lc + 4];
            }
            #pragma unroll
            for (int mi = 0; mi < 2; mi++)
                #pragma unroll
                for (int ni = 0; ni < 4; ni++)
                    mma8(acc[mi][ni], a[mi], b[ni]);
        }
        __syncthreads();
    }

    #pragma unroll
    for (int mi = 0; mi < 2; mi++) {
        int r = m0 + wm * 32 + mi * 16 + lr;
        #pragma unroll
        for (int ni = 0; ni < 4; ni++) {
            int cb = n0 + wn * 32 + ni * 8 + 2 * lc;
            #pragma unroll
            for (int q = 0; q < 2; q++) {
                int cc = cb + q;
                if (cc >= N) continue;
                float bv = act ? bias[cc] : 0.f;
                float v0 = acc[mi][ni][q]     + bv;
                float v1 = acc[mi][ni][q + 2] + bv;
                if (act) { v0 = lrelu_f(v0); v1 = lrelu_f(v1); }
                Out[(long)r * N + cc]       = v0;
                Out[(long)(r + 8) * N + cc] = v1;
            }
        }
    }
}

// =====================================================================
// Per-document attention (one block per d, 256 thr):
//   scores = P@C^T (tf32 mma); diag mask; softmax over i; A -> out
//   rs[i] = sum_j A[i][j]; fri = softmax(enc @ w_root + b_root)
// =====================================================================
__global__ void attn_kernel(const float* __restrict__ P,
                            const float* __restrict__ Cm,
                            const float* __restrict__ enc,
                            const float* __restrict__ w_root,
                            const float* __restrict__ b_root,
                            float* __restrict__ A_out,
                            float* __restrict__ fri_out,
                            float* __restrict__ rs_out)
{
    const int d = blockIdx.x;
    const int t = threadIdx.x;
    const int lane = t & 31;
    const int wid  = t >> 5;
    const int wm = wid >> 1, wn = wid & 1;
    const int lr = lane >> 2, lc = lane & 3;

    __shared__ __align__(16) unsigned Pt[64][33];
    __shared__ __align__(16) unsigned Ct[64][33];
    __shared__ float Ash[64][65];
    __shared__ float sred[64];

    const float* Pd = P   + (long)d * S * H;
    const float* Cd = Cm  + (long)d * S * H;
    const float* Ed = enc + (long)d * S * H;

    float acc[4][4] = {};

    for (int k0 = 0; k0 < H; k0 += 32) {
        for (int u = t; u < 64 * 32; u += 256) {
            int r = u >> 5, k = u & 31;
            bool ok = (k0 + k) < H;
            Pt[r][k] = ok ? f2tf32(Pd[r * H + k0 + k]) : 0u;
            Ct[r][k] = ok ? f2tf32(Cd[r * H + k0 + k]) : 0u;
        }
        __syncthreads();
        #pragma unroll
        for (int ks = 0; ks < 4; ks++) {
            const int kb = ks * 8;
            unsigned a[4], b[4][2];
            int r = wm * 16 + lr;
            a[0] = Pt[r][kb + lc];
            a[1] = Pt[r + 8][kb + lc];
            a[2] = Pt[r][kb + lc + 4];
            a[3] = Pt[r + 8][kb + lc + 4];
            #pragma unroll
            for (int ni = 0; ni < 4; ni++) {
                int c = wn * 32 + ni * 8 + lr;
                b[ni][0] = Ct[c][kb + lc];
                b[ni][1] = Ct[c][kb + lc + 4];
            }
            #pragma unroll
            for (int ni = 0; ni < 4; ni++)
                mma8(acc[ni], a, b[ni]);
        }
        __syncthreads();
    }

    {
        int r = wm * 16 + lr;
        #pragma unroll
        for (int ni = 0; ni < 4; ni++) {
            int cb = wn * 32 + ni * 8 + 2 * lc;
            Ash[r][cb]         = (r == cb)         ? NEGV : acc[ni][0];
            Ash[r][cb + 1]     = (r == cb + 1)     ? NEGV : acc[ni][1];
            Ash[r + 8][cb]     = (r + 8 == cb)     ? NEGV : acc[ni][2];
            Ash[r + 8][cb + 1] = (r + 8 == cb + 1) ? NEGV : acc[ni][3];
        }
    }
    __syncthreads();

    if (t < 64) {
        float m = -1e30f;
        for (int i = 0; i < 64; i++) m = fmaxf(m, Ash[i][t]);
        float ssum = 0.f;
        for (int i = 0; i < 64; i++) {
            float e = __expf(Ash[i][t] - m);
            Ash[i][t] = e;
            ssum += e;
        }
        float inv = 1.f / ssum;
        for (int i = 0; i < 64; i++) Ash[i][t] *= inv;
    }
    __syncthreads();

    for (int u = t; u < 64 * 64; u += 256)
        A_out[(long)d * 4096 + u] = Ash[u >> 6][u & 63];
    if (t < 64) {
        float s = 0.f;
        #pragma unroll 8
        for (int j = 0; j < 64; j++) s += Ash[t][j];
        rs_out[d * 64 + t] = s;
    }

    {
        const float br0 = b_root[0];
        #pragma unroll
        for (int ss = 0; ss < 8; ss++) {
            int s = wid * 8 + ss;
            const float* e = Ed + s * H;
            float p = 0.f;
            for (int h = lane; h < H; h += 32) p += e[h] * w_root[h];
            #pragma unroll
            for (int o = 16; o; o >>= 1) p += __shfl_xor_sync(0xffffffffu, p, o);
            if (lane == 0) sred[s] = p + br0;
        }
    }
    __syncthreads();
    float mye = 0.f;
    if (t < 64) {
        float m = -1e30f;
        for (int u = 0; u < 64; u++) m = fmaxf(m, sred[u]);
        mye = __expf(sred[t] - m);
    }
    __syncthreads();
    if (t < 64) sred[t] = mye;
    __syncthreads();
    if (t < 64) {
        float ssum = 0.f;
        for (int u = 0; u < 64; u++) ssum += sred[u];
        fri_out[d * 64 + t] = mye / ssum;
    }
}

// =====================================================================
// G[d,i,h] = sum_k A[d,k,i] * Y2[d*64+k, h]   (tf32 mma), grid (5, D)
// =====================================================================
__global__ void g_kernel(const float* __restrict__ A_in,
                         const float* __restrict__ Y2,
                         float* __restrict__ G)
{
    const int d  = blockIdx.y;
    const int h0 = blockIdx.x * 64;
    const int t = threadIdx.x;
    const int lane = t & 31;
    const int wid  = t >> 5;
    const int wm = wid >> 1, wn = wid & 1;
    const int lr = lane >> 2, lc = lane & 3;

    __shared__ __align__(16) unsigned Ak[64][65];   // Ak[k][i]
    __shared__ __align__(16) unsigned Ys[64][65];   // Ys[k][h]

    const float* Ad = A_in + (long)d * 4096;
    const float* Yd = Y2 + (long)d * 64 * H;

    for (int u = t; u < 4096; u += 256) {
        int k = u >> 6, i = u & 63;
        Ak[k][i] = f2tf32(Ad[u]);
        int h = h0 + i;
        Ys[k][i] = (h < H) ? f2tf32(Yd[k * H + h]) : 0u;
    }
    __syncthreads();

    float acc[4][4] = {};
    #pragma unroll
    for (int ks = 0; ks < 8; ks++) {
        const int kb = ks * 8;
        unsigned a[4], b[4][2];
        int r = wm * 16 + lr;
        a[0] = Ak[kb + lc][r];
        a[1] = Ak[kb + lc][r + 8];
        a[2] = Ak[kb + lc + 4][r];
        a[3] = Ak[kb + lc + 4][r + 8];
        #pragma unroll
        for (int ni = 0; ni < 4; ni++) {
            int c = wn * 32 + ni * 8 + lr;
            b[ni][0] = Ys[kb + lc][c];
            b[ni][1] = Ys[kb + lc + 4][c];
        }
        #pragma unroll
        for (int ni = 0; ni < 4; ni++)
            mma8(acc[ni], a, b[ni]);
    }

    int r = wm * 16 + lr;
    #pragma unroll
    for (int ni = 0; ni < 4; ni++) {
        int cb = wn * 32 + ni * 8 + 2 * lc;
        #pragma unroll
        for (int q = 0; q < 2; q++) {
            int h = h0 + cb + q;
            if (h >= H) continue;
            G[(long)(d * 64 + r) * H + h]     = acc[ni][q];
            G[(long)(d * 64 + r + 8) * H + h] = acc[ni][q + 2];
        }
    }
}

// =====================================================================
// ri+mean: fin[doc,n] = mean_s lrelu( enc@W1^T + rs*(enc@W3^T)
//                                     + G + fri*v2 + b_r )
// =====================================================================
__global__ void ri_mean_kernel(const float* __restrict__ enc,
                               const float* __restrict__ W_r,   // [H, 900]
                               const float* __restrict__ b_r,
                               const float* __restrict__ G,
                               const float* __restrict__ rs,
                               const float* __restrict__ fri,
                               const float* __restrict__ v2,
                               float* __restrict__ fin)
{
    __shared__ __align__(16) unsigned As[BM][BKP];
    __shared__ __align__(16) unsigned B1s[BN][BKP];
    __shared__ __align__(16) unsigned B3s[BN][BKP];
    __shared__ float red[2][BN];

    const int K = H;
    const int N = H;
    const int tid  = threadIdx.x;
    const int lane = tid & 31;
    const int wid  = tid >> 5;
    const int wm = wid >> 1, wn = wid & 1;
    const int m0 = blockIdx.y * BM;
    const int n0 = blockIdx.x * BN;

    if (tid < 2 * BN) ((float*)red)[tid] = 0.f;

    const int am0 = tid >> 2;
    const int ac  = (tid & 3) * 4;
    const long aoff0 = (long)(m0 + am0) * K;
    const long aoff1 = (long)(m0 + am0 + 64) * K;
    const int  bn     = tid >> 2;
    const bool bvalid = (n0 + bn) < N;
    const long boff   = (long)(n0 + bn) * 900;

    float acc1[2][4][4], acc3[2][4][4];
    #pragma unroll
    for (int i = 0; i < 2; i++)
        #pragma unroll
        for (int j = 0; j < 4; j++)
            #pragma unroll
            for (int q = 0; q < 4; q++) { acc1[i][j][q] = 0.f; acc3[i][j][q] = 0.f; }

    const int lr = lane >> 2, lc = lane & 3;

    for (int k0 = 0; k0 < K; k0 += BK) {
        if (k0 + BK <= K) {
            float4 a0 = *(const float4*)(enc + aoff0 + k0 + ac);
            float4 a1 = *(const float4*)(enc + aoff1 + k0 + ac);
            float4 b1 = bvalid ? *(const float4*)(W_r + boff + k0 + ac) : make_float4(0,0,0,0);
            float4 b3 = bvalid ? *(const float4*)(W_r + boff + 600 + k0 + ac) : make_float4(0,0,0,0);
            *(uint4*)&As[am0][ac]      = make_uint4(f2tf32(a0.x), f2tf32(a0.y), f2tf32(a0.z), f2tf32(a0.w));
            *(uint4*)&As[am0 + 64][ac] = make_uint4(f2tf32(a1.x), f2tf32(a1.y), f2tf32(a1.z), f2tf32(a1.w));
            *(uint4*)&B1s[bn][ac]      = make_uint4(f2tf32(b1.x), f2tf32(b1.y), f2tf32(b1.z), f2tf32(b1.w));
            *(uint4*)&B3s[bn][ac]      = make_uint4(f2tf32(b3.x), f2tf32(b3.y), f2tf32(b3.z), f2tf32(b3.w));
        } else {
            #pragma unroll
            for (int u = 0; u < 4; u++) {
                int k = k0 + ac + u;
                bool kk = k < K;
                As[am0][ac + u]      = kk ? f2tf32(enc[aoff0 + k]) : 0u;
                As[am0 + 64][ac + u] = kk ? f2tf32(enc[aoff1 + k]) : 0u;
                B1s[bn][ac + u]      = (bvalid && kk) ? f2tf32(W_r[boff + k]) : 0u;
                B3s[bn][ac + u]      = (bvalid && kk) ? f2tf32(W_r[boff + 600 + k]) : 0u;
            }
        }
        __syncthreads();
        #pragma unroll
        for (int ks = 0; ks < 2; ks++) {
            const int kb = ks * 8;
            unsigned a[2][4], b1[4][2], b3[4][2];
            #pragma unroll
            for (int mi = 0; mi < 2; mi++) {
                int r = wm * 32 + mi * 16 + lr;
                a[mi][0] = As[r][kb + lc];
                a[mi][1] = As[r + 8][kb + lc];
                a[mi][2] = As[r][kb + lc + 4];
                a[mi][3] = As[r + 8][kb + lc + 4];
            }
            #pragma unroll
            for (int ni = 0; ni < 4; ni++) {
                int c = wn * 32 + ni * 8 + lr;
                b1[ni][0] = B1s[c][kb + lc];
                b1[ni][1] = B1s[c][kb + lc + 4];
                b3[ni][0] = B3s[c][kb + lc];
                b3[ni][1] = B3s[c][kb + lc + 4];
            }
            #pragma unroll
            for (int mi = 0; mi < 2; mi++)
                #pragma unroll
                for (int ni = 0; ni < 4; ni++) {
                    mma8(acc1[mi][ni], a[mi], b1[ni]);
                    mma8(acc3[mi][ni], a[mi], b3[ni]);
                }
        }
        __syncthreads();
    }

    const int dl = wm >> 1;
    #pragma unroll
    for (int ni = 0; ni < 4; ni++) {
        int cb = n0 + wn * 32 + ni * 8 + 2 * lc;
        float s0 = 0.f, s1 = 0.f;
        #pragma unroll
        for (int mi = 0; mi < 2; mi++) {
            int r = m0 + wm * 32 + mi * 16 + lr;
            #pragma unroll
            for (int half = 0; half < 2; half++) {
                int m = r + half * 8;
                float rsm = rs[m], frm = fri[m];
                if (cb < N) {
                    float v = acc1[mi][ni][half * 2] + rsm * acc3[mi][ni][half * 2]
                            + G[(long)m * H + cb] + frm * v2[cb] + b_r[cb];
                    s0 += lrelu_f(v);
                }
                if (cb + 1 < N) {
                    float v = acc1[mi][ni][half * 2 + 1] + rsm * acc3[mi][ni][half * 2 + 1]
                            + G[(long)m * H + cb + 1] + frm * v2[cb + 1] + b_r[cb + 1];
                    s1 += lrelu_f(v);
                }
            }
        }
        #pragma unroll
        for (int o = 4; o < 32; o <<= 1) {
            s0 += __shfl_xor_sync(0xffffffffu, s0, o);
            s1 += __shfl_xor_sync(0xffffffffu, s1, o);
        }
        if (lane < 4) {
            atomicAdd(&red[dl][wn * 32 + ni * 8 + 2 * lc],     s0);
            atomicAdd(&red[dl][wn * 32 + ni * 8 + 2 * lc + 1], s1);
        }
    }
    __syncthreads();
    if (tid < 128) {
        int dloc = tid >> 6, c = tid & 63;
        int col = n0 + c;
        if (col < N)
            fin[(long)(blockIdx.y * 2 + dloc) * H + col] = red[dloc][c] * (1.f / 64.f);
    }
}

// v2[n] = sum_k W_r[n, 300+k] * root_embed[k]
__global__ void v2_kernel(const float* __restrict__ W_r,
                          const float* __restrict__ root_embed,
                          float* __restrict__ v2)
{
    int wid = threadIdx.x >> 5, lane = threadIdx.x & 31;
    int n = blockIdx.x * 8 + wid;
    if (n >= H) return;
    const float* w = W_r + (long)n * 900 + 300;
    float p = 0.f;
    for (int k = lane; k < H; k += 32) p += w[k] * root_embed[k];
    #pragma unroll
    for (int o = 16; o; o >>= 1) p += __shfl_xor_sync(0xffffffffu, p, o);
    if (lane == 0) v2[n] = p;
}

__global__ void cls_kernel(const float* __restrict__ fin,
                           const float* __restrict__ Wc,
                           const float* __restrict__ bc,
                           float* __restrict__ out)
{
    int t = threadIdx.x;
    int d = t >> 1, c = t & 1;
    const float* f = fin + d * H;
    const float* w = Wc + c * H;
    float a = bc[c];
    for (int h = 0; h < H; h++) a += f[h] * w[h];
    out[d * 2 + c] = a;
}

// =====================================================================
extern "C" void kernel_launch(void* const* d_in, const int* in_sizes, int n_in,
                              void* d_out, int out_size)
{
    const int*   word_indices = (const int*)  d_in[0];
    const float* E            = (const float*)d_in[1];
    const float* W_sent       = (const float*)d_in[2];
    const float* b_sent       = (const float*)d_in[3];
    const float* W_par        = (const float*)d_in[4];
    const float* b_par        = (const float*)d_in[5];
    const float* W_ch         = (const float*)d_in[6];
    const float* b_ch         = (const float*)d_in[7];
    const float* w_root       = (const float*)d_in[8];
    const float* b_root       = (const float*)d_in[9];
    const float* root_embed   = (const float*)d_in[10];
    const float* W_r          = (const float*)d_in[11];
    const float* b_r          = (const float*)d_in[12];
    const float* W_cls        = (const float*)d_in[13];
    const float* b_cls        = (const float*)d_in[14];

    float* out_ptr = (float*)d_out;
    float* A_ptr   = out_ptr + D * 2;
    float* fri_ptr = A_ptr + D * S * S;

    float *enc, *Pm, *Cm, *Y2, *G, *rs, *fin, *v2;
    cudaGetSymbolAddress((void**)&enc, g_enc);
    cudaGetSymbolAddress((void**)&Pm,  g_P);
    cudaGetSymbolAddress((void**)&Cm,  g_C);
    cudaGetSymbolAddress((void**)&Y2,  g_Y2);
    cudaGetSymbolAddress((void**)&G,   g_G);
    cudaGetSymbolAddress((void**)&rs,  g_rs);
    cudaGetSymbolAddress((void**)&fin, g_fin);
    cudaGetSymbolAddress((void**)&v2,  g_v2);

    v2_kernel<<<(H + 7) / 8, 256>>>(W_r, root_embed, v2);

    dim3 gEnc((H + BN - 1) / BN, NROWS / BM, 1);
    gemm_tf32_kernel<true><<<gEnc, 256>>>(
        E, word_indices + (L - 1), L,
        W_sent, b_sent, enc,
        nullptr, nullptr, nullptr,
        nullptr, nullptr, nullptr, H, W, W, W, W);

    // P, C (lrelu+bias) and Y2 = enc @ W2^T (linear; W2 rows inside W_r, ld=900)
    dim3 gPCY((H + BN - 1) / BN, NROWS / BM, 3);
    gemm_tf32_kernel<false><<<gPCY, 256>>>(
        enc, nullptr, 0,
        W_par,       b_par,   Pm,
        W_ch,        b_ch,    Cm,
        W_r + 300,   nullptr, Y2,
        H, H, H, H, 900);

    attn_kernel<<<D, 256>>>(Pm, Cm, enc, w_root, b_root, A_ptr, fri_ptr, rs);

    g_kernel<<<dim3(5, D), 256>>>(A_ptr, Y2, G);

    ri_mean_kernel<<<dim3(5, 32), 256>>>(enc, W_r, b_r, G, rs, fri_ptr, v2, fin);

    cls_kernel<<<1, 128>>>(fin, W_cls, b_cls, out_ptr);
}

// round 4
// speedup vs baseline: 2.6058x; 1.0767x over previous
#include <cuda_runtime.h>

#define D 64
#define S 64
#define L 64
#define W 300
#define H 300
#define NROWS (D*S)          // 4096
#define NEGV (-9999999.0f)

// ---------------- device scratch (no allocation allowed) ----------------
__device__ float g_enc[NROWS * H];
__device__ float g_P  [NROWS * H];
__device__ float g_C  [NROWS * H];
__device__ float g_Y2 [NROWS * H];
__device__ float g_G  [NROWS * H];
__device__ float g_rs [NROWS];
__device__ float g_fin[D * H];
__device__ float g_v2 [H];

__device__ __forceinline__ float lrelu_f(float x) { return x > 0.f ? x : 0.01f * x; }

__device__ __forceinline__ unsigned f2tf32(float f) {
    unsigned u;
    asm("cvt.rna.tf32.f32 %0, %1;" : "=r"(u) : "f"(f));
    return u;
}

__device__ __forceinline__ void mma8(float* c, const unsigned* a, const unsigned* b) {
    asm volatile(
        "mma.sync.aligned.m16n8k8.row.col.f32.tf32.tf32.f32 "
        "{%0,%1,%2,%3}, {%4,%5,%6,%7}, {%8,%9}, {%0,%1,%2,%3};"
        : "+f"(c[0]), "+f"(c[1]), "+f"(c[2]), "+f"(c[3])
        : "r"(a[0]), "r"(a[1]), "r"(a[2]), "r"(a[3]), "r"(b[0]), "r"(b[1]));
}

#define BM 128
#define BN 64
#define BK 16
#define BKP 20

// =====================================================================
// TF32 GEMM: Out[M,N] = act( A[M,K] @ B[N,K(ld=ldb)]^T + bias[N] )
// z selects among 3 (B,bias,Out) triples; bias==nullptr => linear.
// =====================================================================
template<bool GATHER>
__global__ void gemm_tf32_kernel(
    const float* __restrict__ Abase, const int* __restrict__ idx, int idxStride,
    const float* __restrict__ B0, const float* __restrict__ bias0, float* __restrict__ Out0,
    const float* __restrict__ B1, const float* __restrict__ bias1, float* __restrict__ Out1,
    const float* __restrict__ B2, const float* __restrict__ bias2, float* __restrict__ Out2,
    int N, int K, int ldb0, int ldb1, int ldb2)
{
    const float* Bw   = B0;
    const float* bias = bias0;
    float*       Out  = Out0;
    int          ldb  = ldb0;
    if (blockIdx.z == 1) { Bw = B1; bias = bias1; Out = Out1; ldb = ldb1; }
    if (blockIdx.z == 2) { Bw = B2; bias = bias2; Out = Out2; ldb = ldb2; }
    const bool act = (bias != nullptr);

    __shared__ __align__(16) unsigned As[BM][BKP];
    __shared__ __align__(16) unsigned Bs[BN][BKP];

    const int tid  = threadIdx.x;
    const int lane = tid & 31;
    const int wid  = tid >> 5;
    const int wm   = wid >> 1;
    const int wn   = wid & 1;
    const int m0   = blockIdx.y * BM;
    const int n0   = blockIdx.x * BN;

    const int am0 = tid >> 2;
    const int ac  = (tid & 3) * 4;
    long aoff0, aoff1;
    if (GATHER) {
        aoff0 = (long)idx[(long)(m0 + am0) * idxStride] * K;
        aoff1 = (long)idx[(long)(m0 + am0 + 64) * idxStride] * K;
    } else {
        aoff0 = (long)(m0 + am0) * K;
        aoff1 = (long)(m0 + am0 + 64) * K;
    }
    const int  bn     = tid >> 2;
    const bool bvalid = (n0 + bn) < N;
    const long boff   = (long)(n0 + bn) * ldb;

    float acc[2][4][4];
    #pragma unroll
    for (int i = 0; i < 2; i++)
        #pragma unroll
        for (int j = 0; j < 4; j++)
            #pragma unroll
            for (int q = 0; q < 4; q++) acc[i][j][q] = 0.f;

    const int lr = lane >> 2;
    const int lc = lane & 3;

    for (int k0 = 0; k0 < K; k0 += BK) {
        if (k0 + BK <= K) {
            float4 a0 = *(const float4*)(Abase + aoff0 + k0 + ac);
            float4 a1 = *(const float4*)(Abase + aoff1 + k0 + ac);
            float4 bv = bvalid ? *(const float4*)(Bw + boff + k0 + ac)
                               : make_float4(0.f, 0.f, 0.f, 0.f);
            *(uint4*)&As[am0][ac]      = make_uint4(f2tf32(a0.x), f2tf32(a0.y), f2tf32(a0.z), f2tf32(a0.w));
            *(uint4*)&As[am0 + 64][ac] = make_uint4(f2tf32(a1.x), f2tf32(a1.y), f2tf32(a1.z), f2tf32(a1.w));
            *(uint4*)&Bs[bn][ac]       = make_uint4(f2tf32(bv.x), f2tf32(bv.y), f2tf32(bv.z), f2tf32(bv.w));
        } else {
            #pragma unroll
            for (int u = 0; u < 4; u++) {
                int k = k0 + ac + u;
                As[am0][ac + u]      = (k < K) ? f2tf32(Abase[aoff0 + k]) : 0u;
                As[am0 + 64][ac + u] = (k < K) ? f2tf32(Abase[aoff1 + k]) : 0u;
                Bs[bn][ac + u]       = (bvalid && k < K) ? f2tf32(Bw[boff + k]) : 0u;
            }
        }
        __syncthreads();
        #pragma unroll
        for (int ks = 0; ks < 2; ks++) {
            const int kb = ks * 8;
            unsigned a[2][4], b[4][2];
            #pragma unroll
            for (int mi = 0; mi < 2; mi++) {
                int r = wm * 32 + mi * 16 + lr;
                a[mi][0] = As[r][kb + lc];
                a[mi][1] = As[r + 8][kb + lc];
                a[mi][2] = As[r][kb + lc + 4];
                a[mi][3] = As[r + 8][kb + lc + 4];
            }
            #pragma unroll
            for (int ni = 0; ni < 4; ni++) {
                int c = wn * 32 + ni * 8 + lr;
                b[ni][0] = Bs[c][kb + lc];
                b[ni][1] = Bs[c][kb + lc + 4];
            }
            #pragma unroll
            for (int mi = 0; mi < 2; mi++)
                #pragma unroll
                for (int ni = 0; ni < 4; ni++)
                    mma8(acc[mi][ni], a[mi], b[ni]);
        }
        __syncthreads();
    }

    #pragma unroll
    for (int mi = 0; mi < 2; mi++) {
        int r = m0 + wm * 32 + mi * 16 + lr;
        #pragma unroll
        for (int ni = 0; ni < 4; ni++) {
            int cb = n0 + wn * 32 + ni * 8 + 2 * lc;
            #pragma unroll
            for (int q = 0; q < 2; q++) {
                int cc = cb + q;
                if (cc >= N) continue;
                float bv = act ? bias[cc] : 0.f;
                float v0 = acc[mi][ni][q]     + bv;
                float v1 = acc[mi][ni][q + 2] + bv;
                if (act) { v0 = lrelu_f(v0); v1 = lrelu_f(v1); }
                Out[(long)r * N + cc]       = v0;
                Out[(long)(r + 8) * N + cc] = v1;
            }
        }
    }
}

// =====================================================================
// Scores + diag mask + column softmax, grid (4, D), 256 thr.
// Block (jb, d) computes A[d, :, jb*16 : jb*16+16].
// Warp grid 4m x 2n; warp tile 16x8 (one mma).
// =====================================================================
__global__ void scores_kernel(const float* __restrict__ P,
                              const float* __restrict__ Cm,
                              float* __restrict__ A_out)
{
    const int d  = blockIdx.y;
    const int j0 = blockIdx.x * 16;
    const int t = threadIdx.x;
    const int lane = t & 31;
    const int wid  = t >> 5;
    const int wm = wid >> 1;    // 0..3
    const int wn = wid & 1;     // 0..1
    const int lr = lane >> 2, lc = lane & 3;

    __shared__ __align__(16) unsigned Pt[64][33];
    __shared__ __align__(16) unsigned Ct[16][36];
    __shared__ float Sh[64][17];

    const float* Pd = P  + (long)d * S * H;
    const float* Cd = Cm + (long)d * S * H;

    float acc[4] = {};

    for (int k0 = 0; k0 < H; k0 += 32) {
        for (int u = t; u < 64 * 32; u += 256) {
            int r = u >> 5, k = u & 31;
            Pt[r][k] = (k0 + k < H) ? f2tf32(Pd[r * H + k0 + k]) : 0u;
        }
        for (int u = t; u < 16 * 32; u += 256) {
            int r = u >> 5, k = u & 31;
            Ct[r][k] = (k0 + k < H) ? f2tf32(Cd[(j0 + r) * H + k0 + k]) : 0u;
        }
        __syncthreads();
        #pragma unroll
        for (int ks = 0; ks < 4; ks++) {
            const int kb = ks * 8;
            unsigned a[4], b[2];
            int r = wm * 16 + lr;
            a[0] = Pt[r][kb + lc];
            a[1] = Pt[r + 8][kb + lc];
            a[2] = Pt[r][kb + lc + 4];
            a[3] = Pt[r + 8][kb + lc + 4];
            int c = wn * 8 + lr;
            b[0] = Ct[c][kb + lc];
            b[1] = Ct[c][kb + lc + 4];
            mma8(acc, a, b);
        }
        __syncthreads();
    }

    // masked scatter into shared
    {
        int r = wm * 16 + lr;
        int cb = wn * 8 + 2 * lc;
        int gc = j0 + cb;
        Sh[r][cb]         = (r == gc)         ? NEGV : acc[0];
        Sh[r][cb + 1]     = (r == gc + 1)     ? NEGV : acc[1];
        Sh[r + 8][cb]     = (r + 8 == gc)     ? NEGV : acc[2];
        Sh[r + 8][cb + 1] = (r + 8 == gc + 1) ? NEGV : acc[3];
    }
    __syncthreads();

    // warp-parallel column softmax: warp w handles local cols 2w, 2w+1
    #pragma unroll
    for (int cc = 0; cc < 2; cc++) {
        int c = wid * 2 + cc;
        float v0 = Sh[lane][c];
        float v1 = Sh[lane + 32][c];
        float m = fmaxf(v0, v1);
        #pragma unroll
        for (int o = 16; o; o >>= 1) m = fmaxf(m, __shfl_xor_sync(0xffffffffu, m, o));
        float e0 = __expf(v0 - m), e1 = __expf(v1 - m);
        float s = e0 + e1;
        #pragma unroll
        for (int o = 16; o; o >>= 1) s += __shfl_xor_sync(0xffffffffu, s, o);
        float inv = 1.f / s;
        Sh[lane][c]      = e0 * inv;
        Sh[lane + 32][c] = e1 * inv;
    }
    __syncthreads();

    // coalesced-ish write: rows of 16 contiguous floats
    for (int u = t; u < 64 * 16; u += 256) {
        int i = u >> 4, j = u & 15;
        A_out[(long)d * 4096 + i * 64 + j0 + j] = Sh[i][j];
    }
}

// =====================================================================
// G[d,i,h] = sum_k A[d,k,i] * Y2[d*64+k, h]  (tf32 mma), grid (5, D).
// Block x==0 additionally computes rs[d,:]; x==1 computes fri[d,:].
// =====================================================================
__global__ void g_kernel(const float* __restrict__ A_in,
                         const float* __restrict__ Y2,
                         const float* __restrict__ enc,
                         const float* __restrict__ w_root,
                         const float* __restrict__ b_root,
                         float* __restrict__ G,
                         float* __restrict__ rs_out,
                         float* __restrict__ fri_out)
{
    const int d  = blockIdx.y;
    const int h0 = blockIdx.x * 64;
    const int t = threadIdx.x;
    const int lane = t & 31;
    const int wid  = t >> 5;
    const int wm = wid >> 1, wn = wid & 1;
    const int lr = lane >> 2, lc = lane & 3;

    __shared__ __align__(16) unsigned Ak[64][65];   // Ak[k][i]
    __shared__ __align__(16) unsigned Ys[64][65];   // Ys[k][h]
    __shared__ float sred[64];

    const float* Ad = A_in + (long)d * 4096;
    const float* Yd = Y2 + (long)d * 64 * H;
    const float* Ed = enc + (long)d * S * H;

    for (int u = t; u < 4096; u += 256) {
        int k = u >> 6, i = u & 63;
        Ak[k][i] = f2tf32(Ad[u]);
        int h = h0 + i;
        Ys[k][i] = (h < H) ? f2tf32(Yd[k * H + h]) : 0u;
    }
    __syncthreads();

    float acc[4][4] = {};
    #pragma unroll
    for (int ks = 0; ks < 8; ks++) {
        const int kb = ks * 8;
        unsigned a[4], b[4][2];
        int r = wm * 16 + lr;
        a[0] = Ak[kb + lc][r];
        a[1] = Ak[kb + lc][r + 8];
        a[2] = Ak[kb + lc + 4][r];
        a[3] = Ak[kb + lc + 4][r + 8];
        #pragma unroll
        for (int ni = 0; ni < 4; ni++) {
            int c = wn * 32 + ni * 8 + lr;
            b[ni][0] = Ys[kb + lc][c];
            b[ni][1] = Ys[kb + lc + 4][c];
        }
        #pragma unroll
        for (int ni = 0; ni < 4; ni++)
            mma8(acc[ni], a, b[ni]);
    }

    {
        int r = wm * 16 + lr;
        #pragma unroll
        for (int ni = 0; ni < 4; ni++) {
            int cb = wn * 32 + ni * 8 + 2 * lc;
            #pragma unroll
            for (int q = 0; q < 2; q++) {
                int h = h0 + cb + q;
                if (h >= H) continue;
                G[(long)(d * 64 + r) * H + h]     = acc[ni][q];
                G[(long)(d * 64 + r + 8) * H + h] = acc[ni][q + 2];
            }
        }
    }

    if (blockIdx.x == 0) {
        // rs[d, r] = sum_j A[d][r][j]; warp handles 8 rows
        #pragma unroll
        for (int rr = 0; rr < 8; rr++) {
            int r = wid * 8 + rr;
            float s = Ad[r * 64 + lane] + Ad[r * 64 + lane + 32];
            #pragma unroll
            for (int o = 16; o; o >>= 1) s += __shfl_xor_sync(0xffffffffu, s, o);
            if (lane == 0) rs_out[d * 64 + r] = s;
        }
    } else if (blockIdx.x == 1) {
        // fri = softmax(enc @ w_root + b_root)
        const float br0 = b_root[0];
        #pragma unroll
        for (int ss = 0; ss < 8; ss++) {
            int s = wid * 8 + ss;
            const float* e = Ed + s * H;
            float p = 0.f;
            for (int h = lane; h < H; h += 32) p += e[h] * w_root[h];
            #pragma unroll
            for (int o = 16; o; o >>= 1) p += __shfl_xor_sync(0xffffffffu, p, o);
            if (lane == 0) sred[s] = p + br0;
        }
        __syncthreads();
        float mye = 0.f;
        if (t < 64) {
            float m = -1e30f;
            for (int u = 0; u < 64; u++) m = fmaxf(m, sred[u]);
            mye = __expf(sred[t] - m);
        }
        __syncthreads();
        if (t < 64) sred[t] = mye;
        __syncthreads();
        if (t < 64) {
            float ssum = 0.f;
            for (int u = 0; u < 64; u++) ssum += sred[u];
            fri_out[d * 64 + t] = mye / ssum;
        }
    }
}

// =====================================================================
// ri+mean: fin[doc,n] = mean_s lrelu( enc@W1^T + rs*(enc@W3^T)
//                                     + G + fri*v2 + b_r )
// =====================================================================
__global__ void ri_mean_kernel(const float* __restrict__ enc,
                               const float* __restrict__ W_r,   // [H, 900]
                               const float* __restrict__ b_r,
                               const float* __restrict__ G,
                               const float* __restrict__ rs,
                               const float* __restrict__ fri,
                               const float* __restrict__ v2,
                               float* __restrict__ fin)
{
    __shared__ __align__(16) unsigned As[BM][BKP];
    __shared__ __align__(16) unsigned B1s[BN][BKP];
    __shared__ __align__(16) unsigned B3s[BN][BKP];
    __shared__ float red[2][BN];

    const int K = H;
    const int N = H;
    const int tid  = threadIdx.x;
    const int lane = tid & 31;
    const int wid  = tid >> 5;
    const int wm = wid >> 1, wn = wid & 1;
    const int m0 = blockIdx.y * BM;
    const int n0 = blockIdx.x * BN;

    if (tid < 2 * BN) ((float*)red)[tid] = 0.f;

    const int am0 = tid >> 2;
    const int ac  = (tid & 3) * 4;
    const long aoff0 = (long)(m0 + am0) * K;
    const long aoff1 = (long)(m0 + am0 + 64) * K;
    const int  bn     = tid >> 2;
    const bool bvalid = (n0 + bn) < N;
    const long boff   = (long)(n0 + bn) * 900;

    float acc1[2][4][4], acc3[2][4][4];
    #pragma unroll
    for (int i = 0; i < 2; i++)
        #pragma unroll
        for (int j = 0; j < 4; j++)
            #pragma unroll
            for (int q = 0; q < 4; q++) { acc1[i][j][q] = 0.f; acc3[i][j][q] = 0.f; }

    const int lr = lane >> 2, lc = lane & 3;

    for (int k0 = 0; k0 < K; k0 += BK) {
        if (k0 + BK <= K) {
            float4 a0 = *(const float4*)(enc + aoff0 + k0 + ac);
            float4 a1 = *(const float4*)(enc + aoff1 + k0 + ac);
            float4 b1 = bvalid ? *(const float4*)(W_r + boff + k0 + ac) : make_float4(0,0,0,0);
            float4 b3 = bvalid ? *(const float4*)(W_r + boff + 600 + k0 + ac) : make_float4(0,0,0,0);
            *(uint4*)&As[am0][ac]      = make_uint4(f2tf32(a0.x), f2tf32(a0.y), f2tf32(a0.z), f2tf32(a0.w));
            *(uint4*)&As[am0 + 64][ac] = make_uint4(f2tf32(a1.x), f2tf32(a1.y), f2tf32(a1.z), f2tf32(a1.w));
            *(uint4*)&B1s[bn][ac]      = make_uint4(f2tf32(b1.x), f2tf32(b1.y), f2tf32(b1.z), f2tf32(b1.w));
            *(uint4*)&B3s[bn][ac]      = make_uint4(f2tf32(b3.x), f2tf32(b3.y), f2tf32(b3.z), f2tf32(b3.w));
        } else {
            #pragma unroll
            for (int u = 0; u < 4; u++) {
                int k = k0 + ac + u;
                bool kk = k < K;
                As[am0][ac + u]      = kk ? f2tf32(enc[aoff0 + k]) : 0u;
                As[am0 + 64][ac + u] = kk ? f2tf32(enc[aoff1 + k]) : 0u;
                B1s[bn][ac + u]      = (bvalid && kk) ? f2tf32(W_r[boff + k]) : 0u;
                B3s[bn][ac + u]      = (bvalid && kk) ? f2tf32(W_r[boff + 600 + k]) : 0u;
            }
        }
        __syncthreads();
        #pragma unroll
        for (int ks = 0; ks < 2; ks++) {
            const int kb = ks * 8;
            unsigned a[2][4], b1[4][2], b3[4][2];
            #pragma unroll
            for (int mi = 0; mi < 2; mi++) {
                int r = wm * 32 + mi * 16 + lr;
                a[mi][0] = As[r][kb + lc];
                a[mi][1] = As[r + 8][kb + lc];
                a[mi][2] = As[r][kb + lc + 4];
                a[mi][3] = As[r + 8][kb + lc + 4];
            }
            #pragma unroll
            for (int ni = 0; ni < 4; ni++) {
                int c = wn * 32 + ni * 8 + lr;
                b1[ni][0] = B1s[c][kb + lc];
                b1[ni][1] = B1s[c][kb + lc + 4];
                b3[ni][0] = B3s[c][kb + lc];
                b3[ni][1] = B3s[c][kb + lc + 4];
            }
            #pragma unroll
            for (int mi = 0; mi < 2; mi++)
                #pragma unroll
                for (int ni = 0; ni < 4; ni++) {
                    mma8(acc1[mi][ni], a[mi], b1[ni]);
                    mma8(acc3[mi][ni], a[mi], b3[ni]);
                }
        }
        __syncthreads();
    }

    const int dl = wm >> 1;
    #pragma unroll
    for (int ni = 0; ni < 4; ni++) {
        int cb = n0 + wn * 32 + ni * 8 + 2 * lc;
        float s0 = 0.f, s1 = 0.f;
        #pragma unroll
        for (int mi = 0; mi < 2; mi++) {
            int r = m0 + wm * 32 + mi * 16 + lr;
            #pragma unroll
            for (int half = 0; half < 2; half++) {
                int m = r + half * 8;
                float rsm = rs[m], frm = fri[m];
                if (cb < N) {
                    float v = acc1[mi][ni][half * 2] + rsm * acc3[mi][ni][half * 2]
                            + G[(long)m * H + cb] + frm * v2[cb] + b_r[cb];
                    s0 += lrelu_f(v);
                }
                if (cb + 1 < N) {
                    float v = acc1[mi][ni][half * 2 + 1] + rsm * acc3[mi][ni][half * 2 + 1]
                            + G[(long)m * H + cb + 1] + frm * v2[cb + 1] + b_r[cb + 1];
                    s1 += lrelu_f(v);
                }
            }
        }
        #pragma unroll
        for (int o = 4; o < 32; o <<= 1) {
            s0 += __shfl_xor_sync(0xffffffffu, s0, o);
            s1 += __shfl_xor_sync(0xffffffffu, s1, o);
        }
        if (lane < 4) {
            atomicAdd(&red[dl][wn * 32 + ni * 8 + 2 * lc],     s0);
            atomicAdd(&red[dl][wn * 32 + ni * 8 + 2 * lc + 1], s1);
        }
    }
    __syncthreads();
    if (tid < 128) {
        int dloc = tid >> 6, c = tid & 63;
        int col = n0 + c;
        if (col < N)
            fin[(long)(blockIdx.y * 2 + dloc) * H + col] = red[dloc][c] * (1.f / 64.f);
    }
}

// v2[n] = sum_k W_r[n, 300+k] * root_embed[k]
__global__ void v2_kernel(const float* __restrict__ W_r,
                          const float* __restrict__ root_embed,
                          float* __restrict__ v2)
{
    int wid = threadIdx.x >> 5, lane = threadIdx.x & 31;
    int n = blockIdx.x * 8 + wid;
    if (n >= H) return;
    const float* w = W_r + (long)n * 900 + 300;
    float p = 0.f;
    for (int k = lane; k < H; k += 32) p += w[k] * root_embed[k];
    #pragma unroll
    for (int o = 16; o; o >>= 1) p += __shfl_xor_sync(0xffffffffu, p, o);
    if (lane == 0) v2[n] = p;
}

__global__ void cls_kernel(const float* __restrict__ fin,
                           const float* __restrict__ Wc,
                           const float* __restrict__ bc,
                           float* __restrict__ out)
{
    int t = threadIdx.x;
    int d = t >> 1, c = t & 1;
    const float* f = fin + d * H;
    const float* w = Wc + c * H;
    float a = bc[c];
    for (int h = 0; h < H; h++) a += f[h] * w[h];
    out[d * 2 + c] = a;
}

// =====================================================================
extern "C" void kernel_launch(void* const* d_in, const int* in_sizes, int n_in,
                              void* d_out, int out_size)
{
    const int*   word_indices = (const int*)  d_in[0];
    const float* E            = (const float*)d_in[1];
    const float* W_sent       = (const float*)d_in[2];
    const float* b_sent       = (const float*)d_in[3];
    const float* W_par        = (const float*)d_in[4];
    const float* b_par        = (const float*)d_in[5];
    const float* W_ch         = (const float*)d_in[6];
    const float* b_ch         = (const float*)d_in[7];
    const float* w_root       = (const float*)d_in[8];
    const float* b_root       = (const float*)d_in[9];
    const float* root_embed   = (const float*)d_in[10];
    const float* W_r          = (const float*)d_in[11];
    const float* b_r          = (const float*)d_in[12];
    const float* W_cls        = (const float*)d_in[13];
    const float* b_cls        = (const float*)d_in[14];

    float* out_ptr = (float*)d_out;
    float* A_ptr   = out_ptr + D * 2;
    float* fri_ptr = A_ptr + D * S * S;

    float *enc, *Pm, *Cm, *Y2, *G, *rs, *fin, *v2;
    cudaGetSymbolAddress((void**)&enc, g_enc);
    cudaGetSymbolAddress((void**)&Pm,  g_P);
    cudaGetSymbolAddress((void**)&Cm,  g_C);
    cudaGetSymbolAddress((void**)&Y2,  g_Y2);
    cudaGetSymbolAddress((void**)&G,   g_G);
    cudaGetSymbolAddress((void**)&rs,  g_rs);
    cudaGetSymbolAddress((void**)&fin, g_fin);
    cudaGetSymbolAddress((void**)&v2,  g_v2);

    v2_kernel<<<(H + 7) / 8, 256>>>(W_r, root_embed, v2);

    dim3 gEnc((H + BN - 1) / BN, NROWS / BM, 1);
    gemm_tf32_kernel<true><<<gEnc, 256>>>(
        E, word_indices + (L - 1), L,
        W_sent, b_sent, enc,
        nullptr, nullptr, nullptr,
        nullptr, nullptr, nullptr, H, W, W, W, W);

    // P, C (lrelu+bias) and Y2 = enc @ W2^T (linear; W2 rows inside W_r, ld=900)
    dim3 gPCY((H + BN - 1) / BN, NROWS / BM, 3);
    gemm_tf32_kernel<false><<<gPCY, 256>>>(
        enc, nullptr, 0,
        W_par,       b_par,   Pm,
        W_ch,        b_ch,    Cm,
        W_r + 300,   nullptr, Y2,
        H, H, H, H, 900);

    // scores + mask + column softmax -> A (in d_out)
    scores_kernel<<<dim3(4, D), 256>>>(Pm, Cm, A_ptr);

    // G = A^T @ Y2 per doc; also rs (x==0) and fri (x==1)
    g_kernel<<<dim3(5, D), 256>>>(A_ptr, Y2, enc, w_root, b_root, G, rs, fri_ptr);

    ri_mean_kernel<<<dim3(5, 32), 256>>>(enc, W_r, b_r, G, rs, fri_ptr, v2, fin);

    cls_kernel<<<1, 128>>>(fin, W_cls, b_cls, out_ptr);
}

// round 5
// speedup vs baseline: 3.1403x; 1.2051x over previous
#include <cuda_runtime.h>

#define D 64
#define S 64
#define L 64
#define W 300
#define H 300
#define NROWS (D*S)          // 4096
#define NEGV (-9999999.0f)

// ---------------- device scratch (no allocation allowed) ----------------
__device__ float g_enc[NROWS * H];
__device__ float g_P  [NROWS * H];
__device__ float g_C  [NROWS * H];
__device__ float g_Y2 [NROWS * H];
__device__ float g_G  [NROWS * H];
__device__ float g_rs [NROWS];
__device__ float g_fin[D * H];
__device__ float g_v2 [H];

__device__ __forceinline__ float lrelu_f(float x) { return x > 0.f ? x : 0.01f * x; }

__device__ __forceinline__ unsigned f2tf32(float f) {
    unsigned u;
    asm("cvt.rna.tf32.f32 %0, %1;" : "=r"(u) : "f"(f));
    return u;
}

__device__ __forceinline__ void mma8(float* c, const unsigned* a, const unsigned* b) {
    asm volatile(
        "mma.sync.aligned.m16n8k8.row.col.f32.tf32.tf32.f32 "
        "{%0,%1,%2,%3}, {%4,%5,%6,%7}, {%8,%9}, {%0,%1,%2,%3};"
        : "+f"(c[0]), "+f"(c[1]), "+f"(c[2]), "+f"(c[3])
        : "r"(a[0]), "r"(a[1]), "r"(a[2]), "r"(a[3]), "r"(b[0]), "r"(b[1]));
}

#define BM 128
#define BN 64
#define BK 16
#define BKP 20

// =====================================================================
// TF32 GEMM: Out[M,N] = act( A[M,K] @ B[N,K(ld=ldb)]^T + bias[N] )
// z selects among 3 (B,bias,Out) triples; bias==nullptr => linear.
// =====================================================================
template<bool GATHER>
__global__ void gemm_tf32_kernel(
    const float* __restrict__ Abase, const int* __restrict__ idx, int idxStride,
    const float* __restrict__ B0, const float* __restrict__ bias0, float* __restrict__ Out0,
    const float* __restrict__ B1, const float* __restrict__ bias1, float* __restrict__ Out1,
    const float* __restrict__ B2, const float* __restrict__ bias2, float* __restrict__ Out2,
    int N, int K, int ldb0, int ldb1, int ldb2)
{
    const float* Bw   = B0;
    const float* bias = bias0;
    float*       Out  = Out0;
    int          ldb  = ldb0;
    if (blockIdx.z == 1) { Bw = B1; bias = bias1; Out = Out1; ldb = ldb1; }
    if (blockIdx.z == 2) { Bw = B2; bias = bias2; Out = Out2; ldb = ldb2; }
    const bool act = (bias != nullptr);

    __shared__ __align__(16) unsigned As[BM][BKP];
    __shared__ __align__(16) unsigned Bs[BN][BKP];

    const int tid  = threadIdx.x;
    const int lane = tid & 31;
    const int wid  = tid >> 5;
    const int wm   = wid >> 1;
    const int wn   = wid & 1;
    const int m0   = blockIdx.y * BM;
    const int n0   = blockIdx.x * BN;

    const int am0 = tid >> 2;
    const int ac  = (tid & 3) * 4;
    long aoff0, aoff1;
    if (GATHER) {
        aoff0 = (long)idx[(long)(m0 + am0) * idxStride] * K;
        aoff1 = (long)idx[(long)(m0 + am0 + 64) * idxStride] * K;
    } else {
        aoff0 = (long)(m0 + am0) * K;
        aoff1 = (long)(m0 + am0 + 64) * K;
    }
    const int  bn     = tid >> 2;
    const bool bvalid = (n0 + bn) < N;
    const long boff   = (long)(n0 + bn) * ldb;

    float acc[2][4][4];
    #pragma unroll
    for (int i = 0; i < 2; i++)
        #pragma unroll
        for (int j = 0; j < 4; j++)
            #pragma unroll
            for (int q = 0; q < 4; q++) acc[i][j][q] = 0.f;

    const int lr = lane >> 2;
    const int lc = lane & 3;

    for (int k0 = 0; k0 < K; k0 += BK) {
        if (k0 + BK <= K) {
            float4 a0 = *(const float4*)(Abase + aoff0 + k0 + ac);
            float4 a1 = *(const float4*)(Abase + aoff1 + k0 + ac);
            float4 bv = bvalid ? *(const float4*)(Bw + boff + k0 + ac)
                               : make_float4(0.f, 0.f, 0.f, 0.f);
            *(uint4*)&As[am0][ac]      = make_uint4(f2tf32(a0.x), f2tf32(a0.y), f2tf32(a0.z), f2tf32(a0.w));
            *(uint4*)&As[am0 + 64][ac] = make_uint4(f2tf32(a1.x), f2tf32(a1.y), f2tf32(a1.z), f2tf32(a1.w));
            *(uint4*)&Bs[bn][ac]       = make_uint4(f2tf32(bv.x), f2tf32(bv.y), f2tf32(bv.z), f2tf32(bv.w));
        } else {
            #pragma unroll
            for (int u = 0; u < 4; u++) {
                int k = k0 + ac + u;
                As[am0][ac + u]      = (k < K) ? f2tf32(Abase[aoff0 + k]) : 0u;
                As[am0 + 64][ac + u] = (k < K) ? f2tf32(Abase[aoff1 + k]) : 0u;
                Bs[bn][ac + u]       = (bvalid && k < K) ? f2tf32(Bw[boff + k]) : 0u;
            }
        }
        __syncthreads();
        #pragma unroll
        for (int ks = 0; ks < 2; ks++) {
            const int kb = ks * 8;
            unsigned a[2][4], b[4][2];
            #pragma unroll
            for (int mi = 0; mi < 2; mi++) {
                int r = wm * 32 + mi * 16 + lr;
                a[mi][0] = As[r][kb + lc];
                a[mi][1] = As[r + 8][kb + lc];
                a[mi][2] = As[r][kb + lc + 4];
                a[mi][3] = As[r + 8][kb + lc + 4];
            }
            #pragma unroll
            for (int ni = 0; ni < 4; ni++) {
                int c = wn * 32 + ni * 8 + lr;
                b[ni][0] = Bs[c][kb + lc];
                b[ni][1] = Bs[c][kb + lc + 4];
            }
            #pragma unroll
            for (int mi = 0; mi < 2; mi++)
                #pragma unroll
                for (int ni = 0; ni < 4; ni++)
                    mma8(acc[mi][ni], a[mi], b[ni]);
        }
        __syncthreads();
    }

    #pragma unroll
    for (int mi = 0; mi < 2; mi++) {
        int r = m0 + wm * 32 + mi * 16 + lr;
        #pragma unroll
        for (int ni = 0; ni < 4; ni++) {
            int cb = n0 + wn * 32 + ni * 8 + 2 * lc;
            #pragma unroll
            for (int q = 0; q < 2; q++) {
                int cc = cb + q;
                if (cc >= N) continue;
                float bv = act ? bias[cc] : 0.f;
                float v0 = acc[mi][ni][q]     + bv;
                float v1 = acc[mi][ni][q + 2] + bv;
                if (act) { v0 = lrelu_f(v0); v1 = lrelu_f(v1); }
                Out[(long)r * N + cc]       = v0;
                Out[(long)(r + 8) * N + cc] = v1;
            }
        }
    }
}

// =====================================================================
// Scores + diag mask + column softmax, grid (4, D), 256 thr.
// Whole K=300 (padded 308) resident in dynamic smem; ONE sync, then an
// uninterrupted 38-step mma chain. Block (jb,d) -> A[d,:,jb*16..+16].
// =====================================================================
#define SPAD 308
#define SCORES_SMEM ((80 * SPAD + 64 * 17) * 4)   // 102,912 B

__global__ void scores_kernel(const float* __restrict__ P,
                              const float* __restrict__ Cm,
                              float* __restrict__ A_out)
{
    extern __shared__ unsigned sdyn[];
    unsigned* Pt = sdyn;                       // [64][SPAD]
    unsigned* Ct = sdyn + 64 * SPAD;           // [16][SPAD]
    float*    Sh = (float*)(sdyn + 80 * SPAD); // [64][17]

    const int d  = blockIdx.y;
    const int j0 = blockIdx.x * 16;
    const int t = threadIdx.x;
    const int lane = t & 31;
    const int wid  = t >> 5;
    const int wm = wid >> 1;    // 0..3
    const int wn = wid & 1;     // 0..1
    const int lr = lane >> 2, lc = lane & 3;

    const float4* Pd4 = (const float4*)(P  + (long)d * S * H);   // 75 float4 per row
    const float4* Cd4 = (const float4*)(Cm + (long)d * S * H);

    // load P whole tile: 64 rows x 76 float4 (col 75 = zero pad)
    for (int u = t; u < 64 * 76; u += 256) {
        int r = u / 76, c4 = u - r * 76;
        float4 v = make_float4(0.f, 0.f, 0.f, 0.f);
        if (c4 < 75) v = Pd4[r * 75 + c4];
        *(uint4*)&Pt[r * SPAD + c4 * 4] =
            make_uint4(f2tf32(v.x), f2tf32(v.y), f2tf32(v.z), f2tf32(v.w));
    }
    // load C slab: 16 rows (j0..j0+15)
    for (int u = t; u < 16 * 76; u += 256) {
        int r = u / 76, c4 = u - r * 76;
        float4 v = make_float4(0.f, 0.f, 0.f, 0.f);
        if (c4 < 75) v = Cd4[(j0 + r) * 75 + c4];
        *(uint4*)&Ct[r * SPAD + c4 * 4] =
            make_uint4(f2tf32(v.x), f2tf32(v.y), f2tf32(v.z), f2tf32(v.w));
    }
    __syncthreads();

    float acc[4] = {};
    {
        const int r = wm * 16 + lr;
        const int c = wn * 8 + lr;
        #pragma unroll
        for (int ks = 0; ks < 38; ks++) {
            const int kb = ks * 8;
            unsigned a[4], b[2];
            a[0] = Pt[r * SPAD + kb + lc];
            a[1] = Pt[(r + 8) * SPAD + kb + lc];
            a[2] = Pt[r * SPAD + kb + lc + 4];
            a[3] = Pt[(r + 8) * SPAD + kb + lc + 4];
            b[0] = Ct[c * SPAD + kb + lc];
            b[1] = Ct[c * SPAD + kb + lc + 4];
            mma8(acc, a, b);
        }
    }

    // masked scatter into shared
    {
        int r = wm * 16 + lr;
        int cb = wn * 8 + 2 * lc;
        int gc = j0 + cb;
        Sh[r * 17 + cb]           = (r == gc)         ? NEGV : acc[0];
        Sh[r * 17 + cb + 1]       = (r == gc + 1)     ? NEGV : acc[1];
        Sh[(r + 8) * 17 + cb]     = (r + 8 == gc)     ? NEGV : acc[2];
        Sh[(r + 8) * 17 + cb + 1] = (r + 8 == gc + 1) ? NEGV : acc[3];
    }
    __syncthreads();

    // warp-parallel column softmax: warp w handles local cols 2w, 2w+1
    #pragma unroll
    for (int cc = 0; cc < 2; cc++) {
        int c = wid * 2 + cc;
        float v0 = Sh[lane * 17 + c];
        float v1 = Sh[(lane + 32) * 17 + c];
        float m = fmaxf(v0, v1);
        #pragma unroll
        for (int o = 16; o; o >>= 1) m = fmaxf(m, __shfl_xor_sync(0xffffffffu, m, o));
        float e0 = __expf(v0 - m), e1 = __expf(v1 - m);
        float s = e0 + e1;
        #pragma unroll
        for (int o = 16; o; o >>= 1) s += __shfl_xor_sync(0xffffffffu, s, o);
        float inv = 1.f / s;
        Sh[lane * 17 + c]        = e0 * inv;
        Sh[(lane + 32) * 17 + c] = e1 * inv;
    }
    __syncthreads();

    for (int u = t; u < 64 * 16; u += 256) {
        int i = u >> 4, j = u & 15;
        A_out[(long)d * 4096 + i * 64 + j0 + j] = Sh[i * 17 + j];
    }
}

// =====================================================================
// G[d,i,h] = sum_k A[d,k,i] * Y2[d*64+k, h]  (tf32 mma), grid (5, D).
// Block x==0 additionally computes rs[d,:]; x==1 computes fri[d,:].
// =====================================================================
__global__ void g_kernel(const float* __restrict__ A_in,
                         const float* __restrict__ Y2,
                         const float* __restrict__ enc,
                         const float* __restrict__ w_root,
                         const float* __restrict__ b_root,
                         float* __restrict__ G,
                         float* __restrict__ rs_out,
                         float* __restrict__ fri_out)
{
    const int d  = blockIdx.y;
    const int h0 = blockIdx.x * 64;
    const int t = threadIdx.x;
    const int lane = t & 31;
    const int wid  = t >> 5;
    const int wm = wid >> 1, wn = wid & 1;
    const int lr = lane >> 2, lc = lane & 3;

    __shared__ __align__(16) unsigned Ak[64][65];   // Ak[k][i]
    __shared__ __align__(16) unsigned Ys[64][65];   // Ys[k][h]
    __shared__ float sred[64];

    const float* Ad = A_in + (long)d * 4096;
    const float* Yd = Y2 + (long)d * 64 * H;
    const float* Ed = enc + (long)d * S * H;

    // vectorized loads: A is 1024 float4, Y2 slab is 64x16 float4
    for (int u = t; u < 1024; u += 256) {
        float4 v = ((const float4*)Ad)[u];
        int k = u >> 4, i = (u & 15) * 4;
        Ak[k][i]     = f2tf32(v.x);
        Ak[k][i + 1] = f2tf32(v.y);
        Ak[k][i + 2] = f2tf32(v.z);
        Ak[k][i + 3] = f2tf32(v.w);
    }
    for (int u = t; u < 1024; u += 256) {
        int k = u >> 4, i = (u & 15) * 4;
        int h = h0 + i;
        float4 v = make_float4(0.f, 0.f, 0.f, 0.f);
        if (h < H) v = *(const float4*)(Yd + k * H + h);
        Ys[k][i]     = f2tf32(v.x);
        Ys[k][i + 1] = f2tf32(v.y);
        Ys[k][i + 2] = f2tf32(v.z);
        Ys[k][i + 3] = f2tf32(v.w);
    }
    __syncthreads();

    float acc[4][4] = {};
    #pragma unroll
    for (int ks = 0; ks < 8; ks++) {
        const int kb = ks * 8;
        unsigned a[4], b[4][2];
        int r = wm * 16 + lr;
        a[0] = Ak[kb + lc][r];
        a[1] = Ak[kb + lc][r + 8];
        a[2] = Ak[kb + lc + 4][r];
        a[3] = Ak[kb + lc + 4][r + 8];
        #pragma unroll
        for (int ni = 0; ni < 4; ni++) {
            int c = wn * 32 + ni * 8 + lr;
            b[ni][0] = Ys[kb + lc][c];
            b[ni][1] = Ys[kb + lc + 4][c];
        }
        #pragma unroll
        for (int ni = 0; ni < 4; ni++)
            mma8(acc[ni], a, b[ni]);
    }

    {
        int r = wm * 16 + lr;
        #pragma unroll
        for (int ni = 0; ni < 4; ni++) {
            int cb = wn * 32 + ni * 8 + 2 * lc;
            #pragma unroll
            for (int q = 0; q < 2; q++) {
                int h = h0 + cb + q;
                if (h >= H) continue;
                G[(long)(d * 64 + r) * H + h]     = acc[ni][q];
                G[(long)(d * 64 + r + 8) * H + h] = acc[ni][q + 2];
            }
        }
    }

    if (blockIdx.x == 0) {
        #pragma unroll
        for (int rr = 0; rr < 8; rr++) {
            int r = wid * 8 + rr;
            float s = Ad[r * 64 + lane] + Ad[r * 64 + lane + 32];
            #pragma unroll
            for (int o = 16; o; o >>= 1) s += __shfl_xor_sync(0xffffffffu, s, o);
            if (lane == 0) rs_out[d * 64 + r] = s;
        }
    } else if (blockIdx.x == 1) {
        const float br0 = b_root[0];
        #pragma unroll
        for (int ss = 0; ss < 8; ss++) {
            int s = wid * 8 + ss;
            const float* e = Ed + s * H;
            float p = 0.f;
            for (int h = lane; h < H; h += 32) p += e[h] * w_root[h];
            #pragma unroll
            for (int o = 16; o; o >>= 1) p += __shfl_xor_sync(0xffffffffu, p, o);
            if (lane == 0) sred[s] = p + br0;
        }
        __syncthreads();
        float mye = 0.f;
        if (t < 64) {
            float m = -1e30f;
            for (int u = 0; u < 64; u++) m = fmaxf(m, sred[u]);
            mye = __expf(sred[t] - m);
        }
        __syncthreads();
        if (t < 64) sred[t] = mye;
        __syncthreads();
        if (t < 64) {
            float ssum = 0.f;
            for (int u = 0; u < 64; u++) ssum += sred[u];
            fri_out[d * 64 + t] = mye / ssum;
        }
    }
}

// =====================================================================
// ri+mean: fin[doc,n] = mean_s lrelu( enc@W1^T + rs*(enc@W3^T)
//                                     + G + fri*v2 + b_r )
// =====================================================================
__global__ void ri_mean_kernel(const float* __restrict__ enc,
                               const float* __restrict__ W_r,   // [H, 900]
                               const float* __restrict__ b_r,
                               const float* __restrict__ G,
                               const float* __restrict__ rs,
                               const float* __restrict__ fri,
                               const float* __restrict__ v2,
                               float* __restrict__ fin)
{
    __shared__ __align__(16) unsigned As[BM][BKP];
    __shared__ __align__(16) unsigned B1s[BN][BKP];
    __shared__ __align__(16) unsigned B3s[BN][BKP];
    __shared__ float red[2][BN];

    const int K = H;
    const int N = H;
    const int tid  = threadIdx.x;
    const int lane = tid & 31;
    const int wid  = tid >> 5;
    const int wm = wid >> 1, wn = wid & 1;
    const int m0 = blockIdx.y * BM;
    const int n0 = blockIdx.x * BN;

    if (tid < 2 * BN) ((float*)red)[tid] = 0.f;

    const int am0 = tid >> 2;
    const int ac  = (tid & 3) * 4;
    const long aoff0 = (long)(m0 + am0) * K;
    const long aoff1 = (long)(m0 + am0 + 64) * K;
    const int  bn     = tid >> 2;
    const bool bvalid = (n0 + bn) < N;
    const long boff   = (long)(n0 + bn) * 900;

    float acc1[2][4][4], acc3[2][4][4];
    #pragma unroll
    for (int i = 0; i < 2; i++)
        #pragma unroll
        for (int j = 0; j < 4; j++)
            #pragma unroll
            for (int q = 0; q < 4; q++) { acc1[i][j][q] = 0.f; acc3[i][j][q] = 0.f; }

    const int lr = lane >> 2, lc = lane & 3;

    for (int k0 = 0; k0 < K; k0 += BK) {
        if (k0 + BK <= K) {
            float4 a0 = *(const float4*)(enc + aoff0 + k0 + ac);
            float4 a1 = *(const float4*)(enc + aoff1 + k0 + ac);
            float4 b1 = bvalid ? *(const float4*)(W_r + boff + k0 + ac) : make_float4(0,0,0,0);
            float4 b3 = bvalid ? *(const float4*)(W_r + boff + 600 + k0 + ac) : make_float4(0,0,0,0);
            *(uint4*)&As[am0][ac]      = make_uint4(f2tf32(a0.x), f2tf32(a0.y), f2tf32(a0.z), f2tf32(a0.w));
            *(uint4*)&As[am0 + 64][ac] = make_uint4(f2tf32(a1.x), f2tf32(a1.y), f2tf32(a1.z), f2tf32(a1.w));
            *(uint4*)&B1s[bn][ac]      = make_uint4(f2tf32(b1.x), f2tf32(b1.y), f2tf32(b1.z), f2tf32(b1.w));
            *(uint4*)&B3s[bn][ac]      = make_uint4(f2tf32(b3.x), f2tf32(b3.y), f2tf32(b3.z), f2tf32(b3.w));
        } else {
            #pragma unroll
            for (int u = 0; u < 4; u++) {
                int k = k0 + ac + u;
                bool kk = k < K;
                As[am0][ac + u]      = kk ? f2tf32(enc[aoff0 + k]) : 0u;
                As[am0 + 64][ac + u] = kk ? f2tf32(enc[aoff1 + k]) : 0u;
                B1s[bn][ac + u]      = (bvalid && kk) ? f2tf32(W_r[boff + k]) : 0u;
                B3s[bn][ac + u]      = (bvalid && kk) ? f2tf32(W_r[boff + 600 + k]) : 0u;
            }
        }
        __syncthreads();
        #pragma unroll
        for (int ks = 0; ks < 2; ks++) {
            const int kb = ks * 8;
            unsigned a[2][4], b1[4][2], b3[4][2];
            #pragma unroll
            for (int mi = 0; mi < 2; mi++) {
                int r = wm * 32 + mi * 16 + lr;
                a[mi][0] = As[r][kb + lc];
                a[mi][1] = As[r + 8][kb + lc];
                a[mi][2] = As[r][kb + lc + 4];
                a[mi][3] = As[r + 8][kb + lc + 4];
            }
            #pragma unroll
            for (int ni = 0; ni < 4; ni++) {
                int c = wn * 32 + ni * 8 + lr;
                b1[ni][0] = B1s[c][kb + lc];
                b1[ni][1] = B1s[c][kb + lc + 4];
                b3[ni][0] = B3s[c][kb + lc];
                b3[ni][1] = B3s[c][kb + lc + 4];
            }
            #pragma unroll
            for (int mi = 0; mi < 2; mi++)
                #pragma unroll
                for (int ni = 0; ni < 4; ni++) {
                    mma8(acc1[mi][ni], a[mi], b1[ni]);
                    mma8(acc3[mi][ni], a[mi], b3[ni]);
                }
        }
        __syncthreads();
    }

    const int dl = wm >> 1;
    #pragma unroll
    for (int ni = 0; ni < 4; ni++) {
        int cb = n0 + wn * 32 + ni * 8 + 2 * lc;
        float s0 = 0.f, s1 = 0.f;
        #pragma unroll
        for (int mi = 0; mi < 2; mi++) {
            int r = m0 + wm * 32 + mi * 16 + lr;
            #pragma unroll
            for (int half = 0; half < 2; half++) {
                int m = r + half * 8;
                float rsm = rs[m], frm = fri[m];
                if (cb < N) {
                    float v = acc1[mi][ni][half * 2] + rsm * acc3[mi][ni][half * 2]
                            + G[(long)m * H + cb] + frm * v2[cb] + b_r[cb];
                    s0 += lrelu_f(v);
                }
                if (cb + 1 < N) {
                    float v = acc1[mi][ni][half * 2 + 1] + rsm * acc3[mi][ni][half * 2 + 1]
                            + G[(long)m * H + cb + 1] + frm * v2[cb + 1] + b_r[cb + 1];
                    s1 += lrelu_f(v);
                }
            }
        }
        #pragma unroll
        for (int o = 4; o < 32; o <<= 1) {
            s0 += __shfl_xor_sync(0xffffffffu, s0, o);
            s1 += __shfl_xor_sync(0xffffffffu, s1, o);
        }
        if (lane < 4) {
            atomicAdd(&red[dl][wn * 32 + ni * 8 + 2 * lc],     s0);
            atomicAdd(&red[dl][wn * 32 + ni * 8 + 2 * lc + 1], s1);
        }
    }
    __syncthreads();
    if (tid < 128) {
        int dloc = tid >> 6, c = tid & 63;
        int col = n0 + c;
        if (col < N)
            fin[(long)(blockIdx.y * 2 + dloc) * H + col] = red[dloc][c] * (1.f / 64.f);
    }
}

// v2[n] = sum_k W_r[n, 300+k] * root_embed[k]
__global__ void v2_kernel(const float* __restrict__ W_r,
                          const float* __restrict__ root_embed,
                          float* __restrict__ v2)
{
    int wid = threadIdx.x >> 5, lane = threadIdx.x & 31;
    int n = blockIdx.x * 8 + wid;
    if (n >= H) return;
    const float* w = W_r + (long)n * 900 + 300;
    float p = 0.f;
    for (int k = lane; k < H; k += 32) p += w[k] * root_embed[k];
    #pragma unroll
    for (int o = 16; o; o >>= 1) p += __shfl_xor_sync(0xffffffffu, p, o);
    if (lane == 0) v2[n] = p;
}

// out[d,c]: one warp per output
__global__ void cls_kernel(const float* __restrict__ fin,
                           const float* __restrict__ Wc,
                           const float* __restrict__ bc,
                           float* __restrict__ out)
{
    int gw = blockIdx.x * (blockDim.x >> 5) + (threadIdx.x >> 5);
    int lane = threadIdx.x & 31;
    if (gw >= 128) return;
    int d = gw >> 1, c = gw & 1;
    const float* f = fin + d * H;
    const float* w = Wc + c * H;
    float p = 0.f;
    for (int h = lane; h < H; h += 32) p += f[h] * w[h];
    #pragma unroll
    for (int o = 16; o; o >>= 1) p += __shfl_xor_sync(0xffffffffu, p, o);
    if (lane == 0) out[d * 2 + c] = p + bc[c];
}

// =====================================================================
extern "C" void kernel_launch(void* const* d_in, const int* in_sizes, int n_in,
                              void* d_out, int out_size)
{
    const int*   word_indices = (const int*)  d_in[0];
    const float* E            = (const float*)d_in[1];
    const float* W_sent       = (const float*)d_in[2];
    const float* b_sent       = (const float*)d_in[3];
    const float* W_par        = (const float*)d_in[4];
    const float* b_par        = (const float*)d_in[5];
    const float* W_ch         = (const float*)d_in[6];
    const float* b_ch         = (const float*)d_in[7];
    const float* w_root       = (const float*)d_in[8];
    const float* b_root       = (const float*)d_in[9];
    const float* root_embed   = (const float*)d_in[10];
    const float* W_r          = (const float*)d_in[11];
    const float* b_r          = (const float*)d_in[12];
    const float* W_cls        = (const float*)d_in[13];
    const float* b_cls        = (const float*)d_in[14];

    float* out_ptr = (float*)d_out;
    float* A_ptr   = out_ptr + D * 2;
    float* fri_ptr = A_ptr + D * S * S;

    float *enc, *Pm, *Cm, *Y2, *G, *rs, *fin, *v2;
    cudaGetSymbolAddress((void**)&enc, g_enc);
    cudaGetSymbolAddress((void**)&Pm,  g_P);
    cudaGetSymbolAddress((void**)&Cm,  g_C);
    cudaGetSymbolAddress((void**)&Y2,  g_Y2);
    cudaGetSymbolAddress((void**)&G,   g_G);
    cudaGetSymbolAddress((void**)&rs,  g_rs);
    cudaGetSymbolAddress((void**)&fin, g_fin);
    cudaGetSymbolAddress((void**)&v2,  g_v2);

    cudaFuncSetAttribute(scores_kernel,
                         cudaFuncAttributeMaxDynamicSharedMemorySize, SCORES_SMEM);

    v2_kernel<<<(H + 7) / 8, 256>>>(W_r, root_embed, v2);

    dim3 gEnc((H + BN - 1) / BN, NROWS / BM, 1);
    gemm_tf32_kernel<true><<<gEnc, 256>>>(
        E, word_indices + (L - 1), L,
        W_sent, b_sent, enc,
        nullptr, nullptr, nullptr,
        nullptr, nullptr, nullptr, H, W, W, W, W);

    // P, C (lrelu+bias) and Y2 = enc @ W2^T (linear; W2 rows inside W_r, ld=900)
    dim3 gPCY((H + BN - 1) / BN, NROWS / BM, 3);
    gemm_tf32_kernel<false><<<gPCY, 256>>>(
        enc, nullptr, 0,
        W_par,       b_par,   Pm,
        W_ch,        b_ch,    Cm,
        W_r + 300,   nullptr, Y2,
        H, H, H, H, 900);

    // scores + mask + column softmax -> A (in d_out)
    scores_kernel<<<dim3(4, D), 256, SCORES_SMEM>>>(Pm, Cm, A_ptr);

    // G = A^T @ Y2 per doc; also rs (x==0) and fri (x==1)
    g_kernel<<<dim3(5, D), 256>>>(A_ptr, Y2, enc, w_root, b_root, G, rs, fri_ptr);

    ri_mean_kernel<<<dim3(5, 32), 256>>>(enc, W_r, b_r, G, rs, fri_ptr, v2, fin);

    cls_kernel<<<8, 512>>>(fin, W_cls, b_cls, out_ptr);
}